// round 9
// baseline (speedup 1.0000x reference)
#include <cuda_runtime.h>
#include <cuda.h>
#include <cuda_bf16.h>
#include <cuda_fp8.h>
#include <math.h>
#include <stdint.h>

// Problem constants (fixed shapes)
#define B_   16
#define C_   384
#define C3   1152
#define HW   4096
#define NH   8
#define DH   48
#define NCH  8
#define CHUNK 512
#define EPSN 1e-12f
#define KTOT 384
#define RSCALE 512.0f
#define INV_RSCALE (1.0f / 512.0f)

// GEMM smem geometry: block 128(M) x 128(N) x 32(K), 3-stage cp.async
// per stage: Ah bf16 128x(32+8pad elems)=10240B | Ah8,Al8 fp8 128x48B |
//            Bh bf16 [k32][128+8 elems]=8704B   | Bl8,Bh8 fp8 [n128][48B]
#define OFF_AH   0
#define OFF_AH8  10240
#define OFF_AL8  16384
#define OFF_BH   22528
#define OFF_BL8  31232
#define OFF_BH8  37376
#define SST      43520
#define NSTG     3
#define GSMEM    (NSTG * SST)    // 130560

// ---------------- scratch (__device__ globals; no runtime alloc) -----------
__device__ __align__(128) float g_qkv[(size_t)B_ * C3 * HW];        // 302 MB
__device__ float g_inv[B_ * 2 * C_];
__device__ float g_Spart[NCH][B_ * NH][DH * DH];
__device__ float g_S[B_ * NH][DH * DH];
// bf16 main-term operands
__device__ __align__(128) __nv_bfloat16 g_W0[C3 * C_];              // Wh [m][k]
__device__ __align__(128) __nv_bfloat16 g_T0[(size_t)B_ * C_ * HW]; // Xh then Vh [k][n]
__device__ __align__(128) __nv_bfloat16 g_We0[B_ * C_ * C_];        // Weh [m][k]
// fp8 correction operands
__device__ __align__(128) uint8_t g_W8h[C3 * C_];                   // fp8(Wh) [m][k]
__device__ __align__(128) uint8_t g_W8l[C3 * C_];                   // fp8(Wl*512)
__device__ __align__(128) uint8_t g_B8h[(size_t)B_ * HW * C_];      // fp8 hi  [n][k] (X then V)
__device__ __align__(128) uint8_t g_B8l[(size_t)B_ * HW * C_];      // fp8 lo*512
__device__ __align__(128) uint8_t g_V8th[(size_t)B_ * C_ * HW];     // V fp8 hi [c][hw] (pre-transpose)
__device__ __align__(128) uint8_t g_V8tl[(size_t)B_ * C_ * HW];
__device__ __align__(128) uint8_t g_We8h[B_ * C_ * C_];
__device__ __align__(128) uint8_t g_We8l[B_ * C_ * C_];

// ---------------- PTX helpers ----------------------------------------------
__device__ __forceinline__ uint32_t smem_u32(const void* p) {
    uint32_t a;
    asm("{ .reg .u64 t; cvta.to.shared.u64 t, %1; cvt.u32.u64 %0, t; }"
        : "=r"(a) : "l"(p));
    return a;
}
__device__ __forceinline__ void ldm_x4(uint32_t* r, uint32_t addr) {
    asm volatile("ldmatrix.sync.aligned.m8n8.x4.shared.b16 {%0,%1,%2,%3}, [%4];"
        : "=r"(r[0]), "=r"(r[1]), "=r"(r[2]), "=r"(r[3]) : "r"(addr));
}
__device__ __forceinline__ void ldm_x4_t(uint32_t* r, uint32_t addr) {
    asm volatile("ldmatrix.sync.aligned.m8n8.x4.trans.shared.b16 {%0,%1,%2,%3}, [%4];"
        : "=r"(r[0]), "=r"(r[1]), "=r"(r[2]), "=r"(r[3]) : "r"(addr));
}
__device__ __forceinline__ void mma16816(float* c, const uint32_t* a,
                                         uint32_t b0, uint32_t b1) {
    asm volatile(
        "mma.sync.aligned.m16n8k16.row.col.f32.bf16.bf16.f32 "
        "{%0,%1,%2,%3}, {%4,%5,%6,%7}, {%8,%9}, {%0,%1,%2,%3};"
        : "+f"(c[0]), "+f"(c[1]), "+f"(c[2]), "+f"(c[3])
        : "r"(a[0]), "r"(a[1]), "r"(a[2]), "r"(a[3]), "r"(b0), "r"(b1));
}
__device__ __forceinline__ void mma_fp8(float* c, const uint32_t* a,
                                        uint32_t b0, uint32_t b1) {
    asm volatile(
        "mma.sync.aligned.m16n8k32.row.col.f32.e4m3.e4m3.f32 "
        "{%0,%1,%2,%3}, {%4,%5,%6,%7}, {%8,%9}, {%0,%1,%2,%3};"
        : "+f"(c[0]), "+f"(c[1]), "+f"(c[2]), "+f"(c[3])
        : "r"(a[0]), "r"(a[1]), "r"(a[2]), "r"(a[3]), "r"(b0), "r"(b1));
}
__device__ __forceinline__ void cpa16(uint32_t s, const void* g) {
    asm volatile("cp.async.cg.shared.global [%0], [%1], 16;" :: "r"(s), "l"(g));
}
__device__ __forceinline__ void cpa_commit() {
    asm volatile("cp.async.commit_group;");
}
template <int N> __device__ __forceinline__ void cpa_wait() {
    asm volatile("cp.async.wait_group %0;" :: "n"(N));
}
__device__ __forceinline__ uint8_t q8(float v) {
    return (uint8_t)__nv_cvt_float_to_fp8(v, __NV_SATFINITE, __NV_E4M3);
}

// ---------------------------------------------------------------------------
// Mixed bf16/fp8 split GEMM.  C = A@B with A,B fp32-valued, decomposed:
//   C = Ah*Bh (bf16 mma) + [fp8(Ah)*fp8(Bl*512) + fp8(Al*512)*fp8(Bh)]/512
// A-side [m][k]; Bh bf16 [k][n]; B8 fp8 [n][k]. Block 128x128x32, 8 warps
// (4M x 2N), warp 32x64. 3-stage cp.async.
// ---------------------------------------------------------------------------
__global__ __launch_bounds__(256, 1)
void gemm_v3(const __nv_bfloat16* __restrict__ Ahg,
             const uint8_t* __restrict__ A8hg, const uint8_t* __restrict__ A8lg,
             size_t aBatch,
             const __nv_bfloat16* __restrict__ Bhg,
             const uint8_t* __restrict__ B8hg, const uint8_t* __restrict__ B8lg,
             float* __restrict__ Cg, size_t cBatch)
{
    extern __shared__ char smem[];
    const uint32_t sbase = smem_u32(smem);

    const int t    = threadIdx.x;
    const int lane = t & 31;
    const int wid  = t >> 5;
    const int b    = blockIdx.z;
    const int m0   = blockIdx.x * 128;
    const int n0   = blockIdx.y * 128;
    const int warpM = (wid & 3) * 32;
    const int warpN = (wid >> 2) * 64;

    const __nv_bfloat16* Ah_g = Ahg + (size_t)b * aBatch + (size_t)m0 * KTOT;
    const uint8_t* A8h_g = A8hg + (size_t)b * aBatch + (size_t)m0 * KTOT;
    const uint8_t* A8l_g = A8lg + (size_t)b * aBatch + (size_t)m0 * KTOT;
    const __nv_bfloat16* Bh_g = Bhg + (size_t)b * C_ * HW;
    const uint8_t* B8h_g = B8hg + (size_t)b * HW * C_;
    const uint8_t* B8l_g = B8lg + (size_t)b * HW * C_;
    float* Cp = Cg + (size_t)b * cBatch;

    const int g  = lane >> 3;
    const int lr = lane & 7;
    // bf16 A: row-group (g&1), col-group (g>>1); rows 80B
    const uint32_t aLaneBf = (uint32_t)(((g & 1) * 8 + lr) * 80 + (g >> 1) * 16);
    // fp8 A: same convention; rows 48B
    const uint32_t aLane8  = (uint32_t)(((g & 1) * 8 + lr) * 48 + (g >> 1) * 16);
    // bf16 B (trans-ldm from [k][n]): k-row (g&1), n-col (g>>1); rows 272B
    const uint32_t bLaneBf = (uint32_t)(((g & 1) * 8 + lr) * 272 + (g >> 1) * 16);
    // fp8 B (plain ldm from [n][k]): n-row (g>>1), k-col (g&1); rows 48B
    const uint32_t bLane8  = (uint32_t)(((g >> 1) * 8 + lr) * 48 + (g & 1) * 16);

    float am[2][8][4], ac[2][8][4];
#pragma unroll
    for (int i = 0; i < 2; i++)
#pragma unroll
        for (int j = 0; j < 8; j++)
#pragma unroll
            for (int e = 0; e < 4; e++) { am[i][j][e] = 0.f; ac[i][j][e] = 0.f; }

    auto load_stage = [&](int kt, int stg) {
        const uint32_t sb = sbase + stg * SST;
#pragma unroll
        for (int it = 0; it < 2; it++) {                  // Ah bf16: 512 chunks
            int c = t + it * 256; int r = c >> 2, kc = c & 3;
            cpa16(sb + OFF_AH + r * 80 + kc * 16,
                  Ah_g + (size_t)r * KTOT + kt * 32 + kc * 8);
        }
        {   int r = t >> 1, kc = t & 1;                   // fp8 A: 256 + 256
            cpa16(sb + OFF_AH8 + r * 48 + kc * 16,
                  A8h_g + (size_t)r * KTOT + kt * 32 + kc * 16);
            cpa16(sb + OFF_AL8 + r * 48 + kc * 16,
                  A8l_g + (size_t)r * KTOT + kt * 32 + kc * 16);
        }
#pragma unroll
        for (int it = 0; it < 2; it++) {                  // Bh bf16: 512 chunks
            int c = t + it * 256; int r = c >> 4, nc = c & 15;
            cpa16(sb + OFF_BH + r * 272 + nc * 16,
                  Bh_g + (size_t)(kt * 32 + r) * HW + n0 + nc * 8);
        }
        {   int r = t >> 1, kc = t & 1;                   // fp8 B: 256 + 256
            cpa16(sb + OFF_BL8 + r * 48 + kc * 16,
                  B8l_g + (size_t)(n0 + r) * KTOT + kt * 32 + kc * 16);
            cpa16(sb + OFF_BH8 + r * 48 + kc * 16,
                  B8h_g + (size_t)(n0 + r) * KTOT + kt * 32 + kc * 16);
        }
        cpa_commit();
    };

    const int KT = KTOT / 32;   // 12
    load_stage(0, 0);
    load_stage(1, 1);

    for (int kt = 0; kt < KT; kt++) {
        if (kt + 2 < KT) load_stage(kt + 2, (kt + 2) % NSTG);
        if (kt + 2 < KT)      cpa_wait<2>();
        else if (kt + 1 < KT) cpa_wait<1>();
        else                  cpa_wait<0>();
        __syncthreads();

        const uint32_t sb = sbase + (kt % NSTG) * SST;

        // ---- main bf16 term (2 x k16) ----
#pragma unroll
        for (int k16 = 0; k16 < 2; k16++) {
            uint32_t Ah[2][4];
#pragma unroll
            for (int i = 0; i < 2; i++)
                ldm_x4(Ah[i], sb + OFF_AH + aLaneBf
                              + (uint32_t)((warpM + i * 16) * 80 + k16 * 32));
#pragma unroll
            for (int p = 0; p < 4; p++) {
                uint32_t r[4];
                ldm_x4_t(r, sb + OFF_BH + bLaneBf
                            + (uint32_t)(k16 * 16 * 272 + (warpN + p * 16) * 2));
#pragma unroll
                for (int i = 0; i < 2; i++) {
                    mma16816(am[i][2 * p],     Ah[i], r[0], r[1]);
                    mma16816(am[i][2 * p + 1], Ah[i], r[2], r[3]);
                }
            }
        }

        // ---- fp8 corrections (one k32 step) ----
        {
            uint32_t A8h[2][4], A8l[2][4];
#pragma unroll
            for (int i = 0; i < 2; i++) {
                uint32_t ao = sb + aLane8 + (uint32_t)((warpM + i * 16) * 48);
                ldm_x4(A8h[i], ao + OFF_AH8);
                ldm_x4(A8l[i], ao + OFF_AL8);
            }
#pragma unroll
            for (int p = 0; p < 4; p++) {
                uint32_t rl[4], rh[4];
                uint32_t bo = sb + bLane8 + (uint32_t)((warpN + p * 16) * 48);
                ldm_x4(rl, bo + OFF_BL8);
                ldm_x4(rh, bo + OFF_BH8);
#pragma unroll
                for (int i = 0; i < 2; i++) {
                    mma_fp8(ac[i][2 * p],     A8h[i], rl[0], rl[1]);  // Ah*Bl
                    mma_fp8(ac[i][2 * p],     A8l[i], rh[0], rh[1]);  // Al*Bh
                    mma_fp8(ac[i][2 * p + 1], A8h[i], rl[2], rl[3]);
                    mma_fp8(ac[i][2 * p + 1], A8l[i], rh[2], rh[3]);
                }
            }
        }
        __syncthreads();
    }

    const int erow = lane >> 2;
    const int ecol = (lane & 3) * 2;
#pragma unroll
    for (int i = 0; i < 2; i++)
#pragma unroll
        for (int j = 0; j < 8; j++) {
            float* base = Cp + (size_t)(m0 + warpM + i * 16 + erow) * HW
                             + n0 + warpN + j * 8 + ecol;
            *(float2*)base = make_float2(
                am[i][j][0] + ac[i][j][0] * INV_RSCALE,
                am[i][j][1] + ac[i][j][1] * INV_RSCALE);
            *(float2*)(base + 8 * HW) = make_float2(
                am[i][j][2] + ac[i][j][2] * INV_RSCALE,
                am[i][j][3] + ac[i][j][3] * INV_RSCALE);
        }
}

// ---------------------------------------------------------------------------
// W prep: Wh bf16 + fp8(Wh) + fp8(Wl*512), all [m][k] natural layout.
// ---------------------------------------------------------------------------
__global__ void wconvert8(const float* __restrict__ src,
                          __nv_bfloat16* __restrict__ dh,
                          uint8_t* __restrict__ d8h, uint8_t* __restrict__ d8l,
                          int n)
{
    int i = blockIdx.x * blockDim.x + threadIdx.x;
    if (i < n) {
        float v = src[i];
        __nv_bfloat16 h = __float2bfloat16(v);
        float hf = __bfloat162float(h);
        dh[i]  = h;
        d8h[i] = q8(hf);
        d8l[i] = q8((v - hf) * RSCALE);
    }
}

// ---------------------------------------------------------------------------
// X prep: tile 32c x 128hw.  Outputs: Xh bf16 [c][hw] (plain) and
// fp8 hi/lo [hw][c] (transposed).
// ---------------------------------------------------------------------------
__global__ __launch_bounds__(256)
void xprep(const float* __restrict__ x,
           __nv_bfloat16* __restrict__ xh,
           uint8_t* __restrict__ x8h, uint8_t* __restrict__ x8l)
{
    __shared__ float s[32][132];
    const int t   = threadIdx.x;
    const int hw0 = blockIdx.x * 128;
    const int c0  = blockIdx.y * 32;
    const int b   = blockIdx.z;
    const float* sp = x + ((size_t)b * C_ + c0) * HW + hw0;

#pragma unroll
    for (int it = 0; it < 4; it++) {
        int i = t + it * 256;
        int r = i >> 5, c4 = (i & 31) * 4;
        *(float4*)&s[r][c4] = *(const float4*)&sp[(size_t)r * HW + c4];
    }
    __syncthreads();

    // plain bf16 hi plane [c][hw]
    {
        int row = t >> 3, cb = (t & 7) * 16;
        __nv_bfloat16* dst = xh + ((size_t)b * C_ + c0 + row) * HW + hw0 + cb;
#pragma unroll
        for (int u = 0; u < 8; u++) {
            float v0 = s[row][cb + 2 * u], v1 = s[row][cb + 2 * u + 1];
            __nv_bfloat16 h0 = __float2bfloat16(v0), h1 = __float2bfloat16(v1);
            uint32_t pk = (uint32_t)__bfloat16_as_ushort(h0) |
                          ((uint32_t)__bfloat16_as_ushort(h1) << 16);
            *(uint32_t*)&dst[2 * u] = pk;
        }
    }
    // transposed fp8 planes [hw][c]
#pragma unroll
    for (int it = 0; it < 4; it++) {
        int i = t + it * 256;
        int hwr = i >> 3, j = (i & 7) * 4;
        uint8_t bh[4], bl[4];
#pragma unroll
        for (int u = 0; u < 4; u++) {
            float v = s[j + u][hwr];
            float hf = __bfloat162float(__float2bfloat16(v));
            bh[u] = q8(hf);
            bl[u] = q8((v - hf) * RSCALE);
        }
        size_t idx = ((size_t)b * HW + hw0 + hwr) * C_ + c0 + j;
        *(uint32_t*)&x8h[idx] = (uint32_t)bh[0] | ((uint32_t)bh[1] << 8) |
                                ((uint32_t)bh[2] << 16) | ((uint32_t)bh[3] << 24);
        *(uint32_t*)&x8l[idx] = (uint32_t)bl[0] | ((uint32_t)bl[1] << 8) |
                                ((uint32_t)bl[2] << 16) | ((uint32_t)bl[3] << 24);
    }
}

// ---------------------------------------------------------------------------
// Depthwise 3x3 SAME conv. q/k: fp32 in-place + fused norms.
// v: Vh bf16 [c][hw] + fp8 hi/lo planes [c][hw] (transposed later).
// ---------------------------------------------------------------------------
__global__ __launch_bounds__(256)
void dwconv3x3(float* __restrict__ qkv, const float* __restrict__ wdw,
               float* __restrict__ inv,
               __nv_bfloat16* __restrict__ V0,
               uint8_t* __restrict__ V8h, uint8_t* __restrict__ V8l)
{
    const int plane = blockIdx.x;
    const int b     = plane / C3;
    const int ch    = plane % C3;
    float* p = qkv + (size_t)plane * HW;

    __shared__ float s[66][72];
    const int t = threadIdx.x;

    if (t < 72)       { s[0][t] = 0.f; s[65][t] = 0.f; }
    else if (t < 136) { s[t - 72 + 1][3]  = 0.f; }
    else if (t < 200) { s[t - 136 + 1][68] = 0.f; }
#pragma unroll
    for (int it = 0; it < 4; it++) {
        int i = t + it * 256;
        int y = i >> 4, x4 = (i & 15) * 4;
        float4 v = *(const float4*)&p[y * 64 + x4];
        *(float4*)&s[y + 1][x4 + 4] = v;
    }

    float w[9];
#pragma unroll
    for (int j = 0; j < 9; j++) w[j] = wdw[ch * 9 + j];
    __syncthreads();

    const bool isv = (ch >= 2 * C_);
    __nv_bfloat16* v0 = 0; uint8_t *v8h = 0, *v8l = 0;
    if (isv) {
        size_t voff = ((size_t)b * C_ + (ch - 2 * C_)) * HW;
        v0 = V0 + voff; v8h = V8h + voff; v8l = V8l + voff;
    }

    const int y  = (t >> 3) * 2;
    const int x8 = (t & 7) * 8;

    float v[4][16];
#pragma unroll
    for (int r = 0; r < 4; r++) {
        *(float4*)&v[r][0]  = *(float4*)&s[y + r][x8];
        *(float4*)&v[r][4]  = *(float4*)&s[y + r][x8 + 4];
        *(float4*)&v[r][8]  = *(float4*)&s[y + r][x8 + 8];
        *(float4*)&v[r][12] = *(float4*)&s[y + r][x8 + 12];
    }

    float o[2][8];
#pragma unroll
    for (int rr = 0; rr < 2; rr++)
#pragma unroll
        for (int j = 0; j < 8; j++) {
            float a = 0.f;
#pragma unroll
            for (int dy = 0; dy < 3; dy++)
#pragma unroll
                for (int dx = 0; dx < 3; dx++)
                    a = fmaf(v[rr + dy][3 + j + dx], w[dy * 3 + dx], a);
            o[rr][j] = a;
        }

    float ss = 0.f;
    if (!isv) {
#pragma unroll
        for (int rr = 0; rr < 2; rr++) {
            *(float4*)&p[(y + rr) * 64 + x8]     = make_float4(o[rr][0], o[rr][1], o[rr][2], o[rr][3]);
            *(float4*)&p[(y + rr) * 64 + x8 + 4] = make_float4(o[rr][4], o[rr][5], o[rr][6], o[rr][7]);
#pragma unroll
            for (int j = 0; j < 8; j++) ss = fmaf(o[rr][j], o[rr][j], ss);
        }
    } else {
#pragma unroll
        for (int rr = 0; rr < 2; rr++) {
            uint32_t hp[4];
            uint8_t b8h[8], b8l[8];
#pragma unroll
            for (int j = 0; j < 4; j++) {
                __nv_bfloat16 ha = __float2bfloat16(o[rr][2 * j]);
                __nv_bfloat16 hb = __float2bfloat16(o[rr][2 * j + 1]);
                hp[j] = (uint32_t)__bfloat16_as_ushort(ha) |
                        ((uint32_t)__bfloat16_as_ushort(hb) << 16);
                float fa = __bfloat162float(ha), fb = __bfloat162float(hb);
                b8h[2 * j]     = q8(fa);
                b8h[2 * j + 1] = q8(fb);
                b8l[2 * j]     = q8((o[rr][2 * j]     - fa) * RSCALE);
                b8l[2 * j + 1] = q8((o[rr][2 * j + 1] - fb) * RSCALE);
            }
            *(uint4*)&v0[(y + rr) * 64 + x8] = make_uint4(hp[0], hp[1], hp[2], hp[3]);
            uint2 ph, pl;
            ph.x = (uint32_t)b8h[0] | ((uint32_t)b8h[1] << 8) | ((uint32_t)b8h[2] << 16) | ((uint32_t)b8h[3] << 24);
            ph.y = (uint32_t)b8h[4] | ((uint32_t)b8h[5] << 8) | ((uint32_t)b8h[6] << 16) | ((uint32_t)b8h[7] << 24);
            pl.x = (uint32_t)b8l[0] | ((uint32_t)b8l[1] << 8) | ((uint32_t)b8l[2] << 16) | ((uint32_t)b8l[3] << 24);
            pl.y = (uint32_t)b8l[4] | ((uint32_t)b8l[5] << 8) | ((uint32_t)b8l[6] << 16) | ((uint32_t)b8l[7] << 24);
            *(uint2*)&v8h[(y + rr) * 64 + x8] = ph;
            *(uint2*)&v8l[(y + rr) * 64 + x8] = pl;
        }
    }

    if (ch < 2 * C_) {
        for (int off = 16; off > 0; off >>= 1)
            ss += __shfl_down_sync(0xffffffffu, ss, off);
        __shared__ float red[8];
        if ((t & 31) == 0) red[t >> 5] = ss;
        __syncthreads();
        if (t == 0) {
            float tot = 0.f;
#pragma unroll
            for (int i = 0; i < 8; i++) tot += red[i];
            inv[b * 2 * C_ + ch] = 1.f / fmaxf(sqrtf(tot), EPSN);
        }
    }
}

// ---------------------------------------------------------------------------
// byte transpose: V fp8 [c][hw] -> [hw][c].  z = b*2 + (0=hi,1=lo).
// ---------------------------------------------------------------------------
__global__ __launch_bounds__(256)
void vtrans(const uint8_t* __restrict__ srcH, const uint8_t* __restrict__ srcL,
            uint8_t* __restrict__ dstH, uint8_t* __restrict__ dstL)
{
    __shared__ uint8_t su[32][132];
    const int t   = threadIdx.x;
    const int hw0 = blockIdx.x * 128;
    const int c0  = blockIdx.y * 32;
    const int z   = blockIdx.z;
    const int b   = z >> 1;
    const uint8_t* src = (z & 1) ? srcL : srcH;
    uint8_t*       dst = (z & 1) ? dstL : dstH;

#pragma unroll
    for (int it = 0; it < 4; it++) {
        int i = t + it * 256;
        int r = i >> 5, q = (i & 31) * 4;
        *(uint32_t*)&su[r][q] =
            *(const uint32_t*)&src[((size_t)b * C_ + c0 + r) * HW + hw0 + q];
    }
    __syncthreads();

#pragma unroll
    for (int it = 0; it < 4; it++) {
        int i = t + it * 256;
        int hwr = i >> 3, j = (i & 7) * 4;
        uint32_t pk = (uint32_t)su[j][hwr] | ((uint32_t)su[j + 1][hwr] << 8) |
                      ((uint32_t)su[j + 2][hwr] << 16) | ((uint32_t)su[j + 3][hwr] << 24);
        *(uint32_t*)&dst[((size_t)b * HW + hw0 + hwr) * C_ + c0 + j] = pk;
    }
}

// ---------------------------------------------------------------------------
// Attention scores split-K partials (unnormalized Gram; aligned smem rows)
// ---------------------------------------------------------------------------
__global__ __launch_bounds__(256)
void attn_scores(const float* __restrict__ qkv)
{
    const int bh    = blockIdx.y;
    const int b     = bh >> 3;
    const int h     = bh & 7;
    const int chunk = blockIdx.x;
    const int t  = threadIdx.x;
    const int tx = t & 15;
    const int ty = t >> 4;

    const float* qbase = qkv + ((size_t)b * C3 + h * DH) * HW;
    const float* kbase = qbase + (size_t)C_ * HW;

    __shared__ float Qs[DH][68];
    __shared__ float Ks[DH][68];

    float acc[3][3];
#pragma unroll
    for (int i = 0; i < 3; i++)
#pragma unroll
        for (int j = 0; j < 3; j++) acc[i][j] = 0.f;

    const int kb = chunk * CHUNK;
    for (int k0 = 0; k0 < CHUNK; k0 += 64) {
        for (int i = t; i < DH * 16; i += 256) {
            int r  = i >> 4;
            int c4 = (i & 15) * 4;
            *(float4*)&Qs[r][c4] = *(const float4*)&qbase[(size_t)r * HW + kb + k0 + c4];
            *(float4*)&Ks[r][c4] = *(const float4*)&kbase[(size_t)r * HW + kb + k0 + c4];
        }
        __syncthreads();

#pragma unroll 16
        for (int kk = 0; kk < 64; kk++) {
            float q0 = Qs[ty     ][kk];
            float q1 = Qs[ty + 16][kk];
            float q2 = Qs[ty + 32][kk];
            float b0 = Ks[tx     ][kk];
            float b1 = Ks[tx + 16][kk];
            float b2 = Ks[tx + 32][kk];
            acc[0][0] = fmaf(q0, b0, acc[0][0]);
            acc[0][1] = fmaf(q0, b1, acc[0][1]);
            acc[0][2] = fmaf(q0, b2, acc[0][2]);
            acc[1][0] = fmaf(q1, b0, acc[1][0]);
            acc[1][1] = fmaf(q1, b1, acc[1][1]);
            acc[1][2] = fmaf(q1, b2, acc[1][2]);
            acc[2][0] = fmaf(q2, b0, acc[2][0]);
            acc[2][1] = fmaf(q2, b1, acc[2][1]);
            acc[2][2] = fmaf(q2, b2, acc[2][2]);
        }
        __syncthreads();
    }

    float* sp = &g_Spart[chunk][bh][0];
#pragma unroll
    for (int i = 0; i < 3; i++)
#pragma unroll
        for (int j = 0; j < 3; j++)
            sp[(ty + 16 * i) * DH + tx + 16 * j] = acc[i][j];
}

__global__ __launch_bounds__(64)
void attn_softmax(const float* __restrict__ temp, const float* __restrict__ inv)
{
    const int bh = blockIdx.x;
    const int b  = bh >> 3;
    const int h  = bh & 7;
    const int r  = threadIdx.x;
    if (r >= DH) return;
    const float* ivq = inv + b * 2 * C_ + h * DH;
    const float* ivk = ivq + C_;
    const float rowscale = ivq[r] * temp[h];

    float vals[DH];
#pragma unroll
    for (int c = 0; c < DH; c++) {
        float s = 0.f;
#pragma unroll
        for (int ch = 0; ch < NCH; ch++)
            s += g_Spart[ch][bh][r * DH + c];
        vals[c] = s * rowscale * ivk[c];
    }
    float m = -INFINITY;
#pragma unroll
    for (int c = 0; c < DH; c++) m = fmaxf(m, vals[c]);
    float sum = 0.f;
#pragma unroll
    for (int c = 0; c < DH; c++) {
        vals[c] = expf(vals[c] - m);
        sum += vals[c];
    }
    float is = 1.f / sum;
#pragma unroll
    for (int c = 0; c < DH; c++)
        g_S[bh][r * DH + c] = vals[c] * is;
}

// ---------------------------------------------------------------------------
// W_eff[b] = W_proj @ blockdiag(A_soft[b]); write bf16 hi + fp8 hi/lo.
// ---------------------------------------------------------------------------
__global__ __launch_bounds__(256)
void weff_kernel(const float* __restrict__ wp,
                 __nv_bfloat16* __restrict__ eh,
                 uint8_t* __restrict__ e8h, uint8_t* __restrict__ e8l)
{
    const int bh = blockIdx.x;
    const int b  = bh >> 3;
    const int h  = bh & 7;
    const int t  = threadIdx.x;

    __shared__ float As[DH][DH + 1];
    for (int i = t; i < DH * DH; i += 256)
        As[i / DH][i % DH] = g_S[bh][i];
    __syncthreads();

    for (int o = t; o < C_; o += 256) {
        float wrow[DH];
#pragma unroll
        for (int d = 0; d < DH; d++) wrow[d] = wp[(size_t)o * C_ + h * DH + d];
#pragma unroll 4
        for (int e = 0; e < DH; e++) {
            float acc = 0.f;
#pragma unroll
            for (int d = 0; d < DH; d++) acc = fmaf(wrow[d], As[d][e], acc);
            size_t idx = ((size_t)b * C_ + o) * C_ + h * DH + e;
            __nv_bfloat16 hi = __float2bfloat16(acc);
            float hf = __bfloat162float(hi);
            eh[idx]  = hi;
            e8h[idx] = q8(hf);
            e8l[idx] = q8((acc - hf) * RSCALE);
        }
    }
}

// ---------------------------------------------------------------------------
extern "C" void kernel_launch(void* const* d_in, const int* in_sizes, int n_in,
                              void* d_out, int out_size)
{
    const float* x      = (const float*)d_in[0];
    const float* w_qkv  = (const float*)d_in[1];
    const float* w_dw   = (const float*)d_in[2];
    const float* w_proj = (const float*)d_in[3];
    const float* temp   = (const float*)d_in[4];
    float* out = (float*)d_out;

    float *qkv, *inv;
    __nv_bfloat16 *W0, *T0, *We0;
    uint8_t *W8h, *W8l, *B8h, *B8l, *V8th, *V8tl, *We8h, *We8l;
    cudaGetSymbolAddress((void**)&qkv, g_qkv);
    cudaGetSymbolAddress((void**)&inv, g_inv);
    cudaGetSymbolAddress((void**)&W0, g_W0);
    cudaGetSymbolAddress((void**)&T0, g_T0);
    cudaGetSymbolAddress((void**)&We0, g_We0);
    cudaGetSymbolAddress((void**)&W8h, g_W8h);
    cudaGetSymbolAddress((void**)&W8l, g_W8l);
    cudaGetSymbolAddress((void**)&B8h, g_B8h);
    cudaGetSymbolAddress((void**)&B8l, g_B8l);
    cudaGetSymbolAddress((void**)&V8th, g_V8th);
    cudaGetSymbolAddress((void**)&V8tl, g_V8tl);
    cudaGetSymbolAddress((void**)&We8h, g_We8h);
    cudaGetSymbolAddress((void**)&We8l, g_We8l);

    cudaFuncSetAttribute(gemm_v3, cudaFuncAttributeMaxDynamicSharedMemorySize, GSMEM);

    // 1) operand prep
    wconvert8<<<(C3 * C_ + 255) / 256, 256>>>(w_qkv, W0, W8h, W8l, C3 * C_);
    xprep<<<dim3(HW / 128, C_ / 32, B_), 256>>>(x, T0, B8h, B8l);
    // 2) qkv = W_qkv @ x  (bf16 main + fp8 corrections)
    gemm_v3<<<dim3(C3 / 128, HW / 128, B_), 256, GSMEM>>>(
        W0, W8h, W8l, 0, T0, B8h, B8l, qkv, (size_t)C3 * HW);
    // 3) dwconv: q/k fp32 + norms; V -> Vh bf16 + fp8 planes
    dwconv3x3<<<B_ * C3, 256>>>(qkv, w_dw, inv, T0, V8th, V8tl);
    // 4) transpose V fp8 planes [c][hw] -> [hw][c]  (overwrites X fp8 bufs)
    vtrans<<<dim3(HW / 128, C_ / 32, B_ * 2), 256>>>(V8th, V8tl, B8h, B8l);
    // 5) attention scores + softmax
    attn_scores<<<dim3(NCH, B_ * NH), 256>>>(qkv);
    attn_softmax<<<B_ * NH, 64>>>(temp, inv);
    // 6) W_eff prep
    weff_kernel<<<B_ * NH, 256>>>(w_proj, We0, We8h, We8l);
    // 7) out = W_eff[b] @ V
    gemm_v3<<<dim3(C_ / 128, HW / 128, B_), 256, GSMEM>>>(
        We0, We8h, We8l, (size_t)C_ * C_, T0, B8h, B8l, out, (size_t)C_ * HW);
}

// round 10
// speedup vs baseline: 1.7140x; 1.7140x over previous
#include <cuda_runtime.h>
#include <cuda.h>
#include <cuda_fp16.h>
#include <math.h>
#include <stdint.h>

// Problem constants (fixed shapes)
#define B_   16
#define C_   384
#define C3   1152
#define HW   4096
#define NH   8
#define DH   48
#define NCH  8
#define CHUNK 512
#define EPSN 1e-12f
#define KTOT 384

// GEMM smem geometry: block 128(M) x 256(N) x 32(K), 3-stage cp.async
// per stage: A fp16 [m128][k32+8pad] | Bh,Bl fp16 [k32][n256+8pad]
#define LDA 40
#define LDB 264
#define A_SZ      (128 * LDA * 2)            // 10240
#define B_TERM_SZ (32 * LDB * 2)             // 16896
#define B_OFF     A_SZ                       // 10240
#define SST       (B_OFF + 2 * B_TERM_SZ)    // 44032
#define NSTG      3
#define GSMEM     (NSTG * SST)               // 132096

// ---------------- scratch (__device__ globals; no runtime alloc) -----------
__device__ __align__(128) float g_qkv[(size_t)B_ * C3 * HW];        // 302 MB
__device__ float g_inv[B_ * 2 * C_];
__device__ float g_Spart[NCH][B_ * NH][DH * DH];
__device__ float g_S[B_ * NH][DH * DH];
__device__ __align__(128) __half g_W0[C3 * C_];                     // Wh [m][k]
__device__ __align__(128) __half g_T0[(size_t)B_ * C_ * HW];        // X/V hi [k][n]
__device__ __align__(128) __half g_T1[(size_t)B_ * C_ * HW];        // X/V lo [k][n]
__device__ __align__(128) __half g_We0[B_ * C_ * C_];               // Weh [m][k]

// ---------------- PTX helpers ----------------------------------------------
__device__ __forceinline__ uint32_t smem_u32(const void* p) {
    uint32_t a;
    asm("{ .reg .u64 t; cvta.to.shared.u64 t, %1; cvt.u32.u64 %0, t; }"
        : "=r"(a) : "l"(p));
    return a;
}
__device__ __forceinline__ void ldm_x4(uint32_t* r, uint32_t addr) {
    asm volatile("ldmatrix.sync.aligned.m8n8.x4.shared.b16 {%0,%1,%2,%3}, [%4];"
        : "=r"(r[0]), "=r"(r[1]), "=r"(r[2]), "=r"(r[3]) : "r"(addr));
}
__device__ __forceinline__ void ldm_x4_t(uint32_t* r, uint32_t addr) {
    asm volatile("ldmatrix.sync.aligned.m8n8.x4.trans.shared.b16 {%0,%1,%2,%3}, [%4];"
        : "=r"(r[0]), "=r"(r[1]), "=r"(r[2]), "=r"(r[3]) : "r"(addr));
}
__device__ __forceinline__ void mma_h(float* c, const uint32_t* a,
                                      uint32_t b0, uint32_t b1) {
    asm volatile(
        "mma.sync.aligned.m16n8k16.row.col.f32.f16.f16.f32 "
        "{%0,%1,%2,%3}, {%4,%5,%6,%7}, {%8,%9}, {%0,%1,%2,%3};"
        : "+f"(c[0]), "+f"(c[1]), "+f"(c[2]), "+f"(c[3])
        : "r"(a[0]), "r"(a[1]), "r"(a[2]), "r"(a[3]), "r"(b0), "r"(b1));
}
__device__ __forceinline__ void cpa16(uint32_t s, const void* g) {
    asm volatile("cp.async.cg.shared.global [%0], [%1], 16;" :: "r"(s), "l"(g));
}
__device__ __forceinline__ void cpa_commit() {
    asm volatile("cp.async.commit_group;");
}
template <int N> __device__ __forceinline__ void cpa_wait() {
    asm volatile("cp.async.wait_group %0;" :: "n"(N));
}

// ---------------------------------------------------------------------------
// fp16 2-term GEMM: C[b][M,4096] = Ah[M,384] @ (Bh + Bl)[384,4096].
// A fp16 [m][k] (weights, single-rounded); B hi/lo fp16 planes [k][n].
// Block 128x256x32, 8 warps (2Mx4N), warp 64x64, 3-stage cp.async.
// grid (x = M/128, y = 4096/256, z = batch) -> consecutive blocks share B.
// ---------------------------------------------------------------------------
__global__ __launch_bounds__(256, 1)
void gemm_h2(const __half* __restrict__ Ahg, size_t aBatch,
             const __half* __restrict__ B0g, const __half* __restrict__ B1g,
             float* __restrict__ Cg, size_t cBatch)
{
    extern __shared__ char smem[];
    const uint32_t sbase = smem_u32(smem);

    const int t    = threadIdx.x;
    const int lane = t & 31;
    const int wid  = t >> 5;
    const int b    = blockIdx.z;
    const int m0   = blockIdx.x * 128;
    const int n0   = blockIdx.y * 256;
    const int warpM = (wid >> 2) * 64;
    const int warpN = (wid & 3) * 64;

    const __half* Asrc = Ahg + (size_t)b * aBatch + (size_t)m0 * KTOT;
    const __half* Bsrc[2] = { B0g + (size_t)b * C_ * HW,
                              B1g + (size_t)b * C_ * HW };
    float* Cp = Cg + (size_t)b * cBatch;

    const int g  = lane >> 3;
    const int lr = lane & 7;
    const uint32_t aLane = (uint32_t)(((g & 1) * 8 + lr) * LDA + (g >> 1) * 8) * 2;
    const uint32_t bLane = (uint32_t)(((g & 1) * 8 + lr) * LDB + (g >> 1) * 8) * 2;

    float acc[4][8][4];
#pragma unroll
    for (int i = 0; i < 4; i++)
#pragma unroll
        for (int j = 0; j < 8; j++)
#pragma unroll
            for (int e = 0; e < 4; e++) acc[i][j][e] = 0.f;

    auto load_stage = [&](int kt, int stg) {
        const uint32_t sb = sbase + stg * SST;
#pragma unroll
        for (int it = 0; it < 2; it++) {          // A: 512 x 16B
            int c = t + it * 256;
            int r = c >> 2, kc = c & 3;
            cpa16(sb + r * (LDA * 2) + kc * 16,
                  Asrc + (size_t)r * KTOT + kt * 32 + kc * 8);
        }
#pragma unroll
        for (int it = 0; it < 8; it++) {          // B: 2048 x 16B (2 planes)
            int c = t + it * 256;
            int term = c >> 10, j = c & 1023;
            int r = j >> 5, nc = j & 31;
            cpa16(sb + B_OFF + term * B_TERM_SZ + r * (LDB * 2) + nc * 16,
                  Bsrc[term] + (size_t)(kt * 32 + r) * HW + n0 + nc * 8);
        }
        cpa_commit();
    };

    const int KT = KTOT / 32;   // 12
    load_stage(0, 0);
    load_stage(1, 1);

    for (int kt = 0; kt < KT; kt++) {
        if (kt + 2 < KT) load_stage(kt + 2, (kt + 2) % NSTG);
        if (kt + 2 < KT)      cpa_wait<2>();
        else if (kt + 1 < KT) cpa_wait<1>();
        else                  cpa_wait<0>();
        __syncthreads();

        const uint32_t sb = sbase + (kt % NSTG) * SST;
#pragma unroll
        for (int k16 = 0; k16 < 2; k16++) {
            uint32_t Ah[4][4];
#pragma unroll
            for (int i = 0; i < 4; i++)
                ldm_x4(Ah[i], sb + aLane
                              + (uint32_t)((warpM + i * 16) * LDA + k16 * 16) * 2);
            // ---- B hi plane ----
            {
                uint32_t Bf[8][2];
#pragma unroll
                for (int p = 0; p < 4; p++) {
                    uint32_t r[4];
                    uint32_t bo = sb + B_OFF + bLane
                                + (uint32_t)(k16 * 16 * LDB + warpN + p * 16) * 2;
                    ldm_x4_t(r, bo);
                    Bf[p * 2][0] = r[0]; Bf[p * 2][1] = r[1];
                    Bf[p * 2 + 1][0] = r[2]; Bf[p * 2 + 1][1] = r[3];
                }
#pragma unroll
                for (int i = 0; i < 4; i++)
#pragma unroll
                    for (int j = 0; j < 8; j++)
                        mma_h(acc[i][j], Ah[i], Bf[j][0], Bf[j][1]);
            }
            // ---- B lo plane ----
            {
                uint32_t Bf[8][2];
#pragma unroll
                for (int p = 0; p < 4; p++) {
                    uint32_t r[4];
                    uint32_t bo = sb + B_OFF + B_TERM_SZ + bLane
                                + (uint32_t)(k16 * 16 * LDB + warpN + p * 16) * 2;
                    ldm_x4_t(r, bo);
                    Bf[p * 2][0] = r[0]; Bf[p * 2][1] = r[1];
                    Bf[p * 2 + 1][0] = r[2]; Bf[p * 2 + 1][1] = r[3];
                }
#pragma unroll
                for (int i = 0; i < 4; i++)
#pragma unroll
                    for (int j = 0; j < 8; j++)
                        mma_h(acc[i][j], Ah[i], Bf[j][0], Bf[j][1]);
            }
        }
        __syncthreads();
    }

    const int erow = lane >> 2;
    const int ecol = (lane & 3) * 2;
#pragma unroll
    for (int i = 0; i < 4; i++)
#pragma unroll
        for (int j = 0; j < 8; j++) {
            float* base = Cp + (size_t)(m0 + warpM + i * 16 + erow) * HW
                             + n0 + warpN + j * 8 + ecol;
            *(float2*)base = make_float2(acc[i][j][0], acc[i][j][1]);
            *(float2*)(base + 8 * HW) = make_float2(acc[i][j][2], acc[i][j][3]);
        }
}

// ---------------------------------------------------------------------------
// W fp32 -> fp16 single-rounded plane
// ---------------------------------------------------------------------------
__global__ void wconvert(const float* __restrict__ src,
                         __half* __restrict__ dh, int n)
{
    int i = blockIdx.x * blockDim.x + threadIdx.x;
    if (i < n) dh[i] = __float2half(src[i]);
}

// ---------------------------------------------------------------------------
// X fp32 -> fp16 hi/lo split planes (linear [k][n] layout preserved)
// ---------------------------------------------------------------------------
__global__ __launch_bounds__(256)
void xsplit(const float* __restrict__ src,
            __half* __restrict__ d0, __half* __restrict__ d1, int n4)
{
    int i = blockIdx.x * 256 + threadIdx.x;
    if (i >= n4) return;
    float4 v = ((const float4*)src)[i];
    __half h0 = __float2half(v.x), h1 = __float2half(v.y);
    __half h2 = __float2half(v.z), h3 = __float2half(v.w);
    __half l0 = __float2half(v.x - __half2float(h0));
    __half l1 = __float2half(v.y - __half2float(h1));
    __half l2 = __float2half(v.z - __half2float(h2));
    __half l3 = __float2half(v.w - __half2float(h3));
    uint2 hp = make_uint2(
        (uint32_t)__half_as_ushort(h0) | ((uint32_t)__half_as_ushort(h1) << 16),
        (uint32_t)__half_as_ushort(h2) | ((uint32_t)__half_as_ushort(h3) << 16));
    uint2 lp = make_uint2(
        (uint32_t)__half_as_ushort(l0) | ((uint32_t)__half_as_ushort(l1) << 16),
        (uint32_t)__half_as_ushort(l2) | ((uint32_t)__half_as_ushort(l3) << 16));
    ((uint2*)d0)[i] = hp;
    ((uint2*)d1)[i] = lp;
}

// ---------------------------------------------------------------------------
// Depthwise 3x3 SAME conv, row-pair stencil. q/k fp32 in-place + fused norms;
// v -> fp16 hi/lo split planes.
// ---------------------------------------------------------------------------
__global__ __launch_bounds__(256)
void dwconv3x3(float* __restrict__ qkv, const float* __restrict__ wdw,
               float* __restrict__ inv,
               __half* __restrict__ V0, __half* __restrict__ V1)
{
    const int plane = blockIdx.x;
    const int b     = plane / C3;
    const int ch    = plane % C3;
    float* p = qkv + (size_t)plane * HW;

    __shared__ float s[66][72];
    const int t = threadIdx.x;

    if (t < 72)       { s[0][t] = 0.f; s[65][t] = 0.f; }
    else if (t < 136) { s[t - 72 + 1][3]  = 0.f; }
    else if (t < 200) { s[t - 136 + 1][68] = 0.f; }
#pragma unroll
    for (int it = 0; it < 4; it++) {
        int i = t + it * 256;
        int y = i >> 4, x4 = (i & 15) * 4;
        float4 v = *(const float4*)&p[y * 64 + x4];
        *(float4*)&s[y + 1][x4 + 4] = v;
    }

    float w[9];
#pragma unroll
    for (int j = 0; j < 9; j++) w[j] = wdw[ch * 9 + j];
    __syncthreads();

    const bool isv = (ch >= 2 * C_);
    __half *v0 = 0, *v1 = 0;
    if (isv) {
        size_t voff = ((size_t)b * C_ + (ch - 2 * C_)) * HW;
        v0 = V0 + voff; v1 = V1 + voff;
    }

    const int y  = (t >> 3) * 2;
    const int x8 = (t & 7) * 8;

    float v[4][16];
#pragma unroll
    for (int r = 0; r < 4; r++) {
        *(float4*)&v[r][0]  = *(float4*)&s[y + r][x8];
        *(float4*)&v[r][4]  = *(float4*)&s[y + r][x8 + 4];
        *(float4*)&v[r][8]  = *(float4*)&s[y + r][x8 + 8];
        *(float4*)&v[r][12] = *(float4*)&s[y + r][x8 + 12];
    }

    float o[2][8];
#pragma unroll
    for (int rr = 0; rr < 2; rr++)
#pragma unroll
        for (int j = 0; j < 8; j++) {
            float a = 0.f;
#pragma unroll
            for (int dy = 0; dy < 3; dy++)
#pragma unroll
                for (int dx = 0; dx < 3; dx++)
                    a = fmaf(v[rr + dy][3 + j + dx], w[dy * 3 + dx], a);
            o[rr][j] = a;
        }

    float ss = 0.f;
    if (!isv) {
#pragma unroll
        for (int rr = 0; rr < 2; rr++) {
            *(float4*)&p[(y + rr) * 64 + x8]     = make_float4(o[rr][0], o[rr][1], o[rr][2], o[rr][3]);
            *(float4*)&p[(y + rr) * 64 + x8 + 4] = make_float4(o[rr][4], o[rr][5], o[rr][6], o[rr][7]);
#pragma unroll
            for (int j = 0; j < 8; j++) ss = fmaf(o[rr][j], o[rr][j], ss);
        }
    } else {
#pragma unroll
        for (int rr = 0; rr < 2; rr++) {
            uint32_t hp[4], lp[4];
#pragma unroll
            for (int j = 0; j < 4; j++) {
                __half ha = __float2half(o[rr][2 * j]);
                __half hb = __float2half(o[rr][2 * j + 1]);
                __half la = __float2half(o[rr][2 * j]     - __half2float(ha));
                __half lb = __float2half(o[rr][2 * j + 1] - __half2float(hb));
                hp[j] = (uint32_t)__half_as_ushort(ha) |
                        ((uint32_t)__half_as_ushort(hb) << 16);
                lp[j] = (uint32_t)__half_as_ushort(la) |
                        ((uint32_t)__half_as_ushort(lb) << 16);
            }
            *(uint4*)&v0[(y + rr) * 64 + x8] = make_uint4(hp[0], hp[1], hp[2], hp[3]);
            *(uint4*)&v1[(y + rr) * 64 + x8] = make_uint4(lp[0], lp[1], lp[2], lp[3]);
        }
    }

    if (ch < 2 * C_) {
        for (int off = 16; off > 0; off >>= 1)
            ss += __shfl_down_sync(0xffffffffu, ss, off);
        __shared__ float red[8];
        if ((t & 31) == 0) red[t >> 5] = ss;
        __syncthreads();
        if (t == 0) {
            float tot = 0.f;
#pragma unroll
            for (int i = 0; i < 8; i++) tot += red[i];
            inv[b * 2 * C_ + ch] = 1.f / fmaxf(sqrtf(tot), EPSN);
        }
    }
}

// ---------------------------------------------------------------------------
// Attention scores split-K partials (unnormalized Gram; aligned smem rows)
// ---------------------------------------------------------------------------
__global__ __launch_bounds__(256)
void attn_scores(const float* __restrict__ qkv)
{
    const int bh    = blockIdx.y;
    const int b     = bh >> 3;
    const int h     = bh & 7;
    const int chunk = blockIdx.x;
    const int t  = threadIdx.x;
    const int tx = t & 15;
    const int ty = t >> 4;

    const float* qbase = qkv + ((size_t)b * C3 + h * DH) * HW;
    const float* kbase = qbase + (size_t)C_ * HW;

    __shared__ float Qs[DH][68];
    __shared__ float Ks[DH][68];

    float acc[3][3];
#pragma unroll
    for (int i = 0; i < 3; i++)
#pragma unroll
        for (int j = 0; j < 3; j++) acc[i][j] = 0.f;

    const int kb = chunk * CHUNK;
    for (int k0 = 0; k0 < CHUNK; k0 += 64) {
        for (int i = t; i < DH * 16; i += 256) {
            int r  = i >> 4;
            int c4 = (i & 15) * 4;
            *(float4*)&Qs[r][c4] = *(const float4*)&qbase[(size_t)r * HW + kb + k0 + c4];
            *(float4*)&Ks[r][c4] = *(const float4*)&kbase[(size_t)r * HW + kb + k0 + c4];
        }
        __syncthreads();

#pragma unroll 16
        for (int kk = 0; kk < 64; kk++) {
            float q0 = Qs[ty     ][kk];
            float q1 = Qs[ty + 16][kk];
            float q2 = Qs[ty + 32][kk];
            float b0 = Ks[tx     ][kk];
            float b1 = Ks[tx + 16][kk];
            float b2 = Ks[tx + 32][kk];
            acc[0][0] = fmaf(q0, b0, acc[0][0]);
            acc[0][1] = fmaf(q0, b1, acc[0][1]);
            acc[0][2] = fmaf(q0, b2, acc[0][2]);
            acc[1][0] = fmaf(q1, b0, acc[1][0]);
            acc[1][1] = fmaf(q1, b1, acc[1][1]);
            acc[1][2] = fmaf(q1, b2, acc[1][2]);
            acc[2][0] = fmaf(q2, b0, acc[2][0]);
            acc[2][1] = fmaf(q2, b1, acc[2][1]);
            acc[2][2] = fmaf(q2, b2, acc[2][2]);
        }
        __syncthreads();
    }

    float* sp = &g_Spart[chunk][bh][0];
#pragma unroll
    for (int i = 0; i < 3; i++)
#pragma unroll
        for (int j = 0; j < 3; j++)
            sp[(ty + 16 * i) * DH + tx + 16 * j] = acc[i][j];
}

// reduce partials, apply rank-1 norm scaling + temperature, row softmax
__global__ __launch_bounds__(64)
void attn_softmax(const float* __restrict__ temp, const float* __restrict__ inv)
{
    const int bh = blockIdx.x;
    const int b  = bh >> 3;
    const int h  = bh & 7;
    const int r  = threadIdx.x;
    if (r >= DH) return;
    const float* ivq = inv + b * 2 * C_ + h * DH;
    const float* ivk = ivq + C_;
    const float rowscale = ivq[r] * temp[h];

    float vals[DH];
#pragma unroll
    for (int c = 0; c < DH; c++) {
        float s = 0.f;
#pragma unroll
        for (int ch = 0; ch < NCH; ch++)
            s += g_Spart[ch][bh][r * DH + c];
        vals[c] = s * rowscale * ivk[c];
    }
    float m = -INFINITY;
#pragma unroll
    for (int c = 0; c < DH; c++) m = fmaxf(m, vals[c]);
    float sum = 0.f;
#pragma unroll
    for (int c = 0; c < DH; c++) {
        vals[c] = expf(vals[c] - m);
        sum += vals[c];
    }
    float is = 1.f / sum;
#pragma unroll
    for (int c = 0; c < DH; c++)
        g_S[bh][r * DH + c] = vals[c] * is;
}

// ---------------------------------------------------------------------------
// W_eff[b] = W_proj @ blockdiag(A_soft[b]) ; fp16 single plane. grid = B_*NH.
// ---------------------------------------------------------------------------
__global__ __launch_bounds__(256)
void weff_kernel(const float* __restrict__ wp, __half* __restrict__ eh)
{
    const int bh = blockIdx.x;
    const int b  = bh >> 3;
    const int h  = bh & 7;
    const int t  = threadIdx.x;

    __shared__ float As[DH][DH + 1];
    for (int i = t; i < DH * DH; i += 256)
        As[i / DH][i % DH] = g_S[bh][i];
    __syncthreads();

    for (int o = t; o < C_; o += 256) {
        float wrow[DH];
#pragma unroll
        for (int d = 0; d < DH; d++) wrow[d] = wp[(size_t)o * C_ + h * DH + d];
#pragma unroll 4
        for (int e = 0; e < DH; e++) {
            float acc = 0.f;
#pragma unroll
            for (int d = 0; d < DH; d++) acc = fmaf(wrow[d], As[d][e], acc);
            eh[((size_t)b * C_ + o) * C_ + h * DH + e] = __float2half(acc);
        }
    }
}

// ---------------------------------------------------------------------------
extern "C" void kernel_launch(void* const* d_in, const int* in_sizes, int n_in,
                              void* d_out, int out_size)
{
    const float* x      = (const float*)d_in[0];
    const float* w_qkv  = (const float*)d_in[1];
    const float* w_dw   = (const float*)d_in[2];
    const float* w_proj = (const float*)d_in[3];
    const float* temp   = (const float*)d_in[4];
    float* out = (float*)d_out;

    float *qkv, *inv;
    __half *W0, *T0, *T1, *We0;
    cudaGetSymbolAddress((void**)&qkv, g_qkv);
    cudaGetSymbolAddress((void**)&inv, g_inv);
    cudaGetSymbolAddress((void**)&W0, g_W0);
    cudaGetSymbolAddress((void**)&T0, g_T0);
    cudaGetSymbolAddress((void**)&T1, g_T1);
    cudaGetSymbolAddress((void**)&We0, g_We0);

    cudaFuncSetAttribute(gemm_h2, cudaFuncAttributeMaxDynamicSharedMemorySize, GSMEM);

    // 1) W -> fp16 ; X -> fp16 hi/lo planes
    wconvert<<<(C3 * C_ + 255) / 256, 256>>>(w_qkv, W0, C3 * C_);
    xsplit<<<(B_ * C_ * HW / 4 + 255) / 256, 256>>>(x, T0, T1, B_ * C_ * HW / 4);
    // 2) qkv = W_qkv @ (Xh + Xl)
    gemm_h2<<<dim3(C3 / 128, HW / 256, B_), 256, GSMEM>>>(
        W0, 0, T0, T1, qkv, (size_t)C3 * HW);
    // 3) dwconv: q/k fp32 in-place + norms; v -> fp16 hi/lo planes
    dwconv3x3<<<B_ * C3, 256>>>(qkv, w_dw, inv, T0, T1);
    // 4) attention scores (unnormalized Gram) + softmax (applies norms)
    attn_scores<<<dim3(NCH, B_ * NH), 256>>>(qkv);
    attn_softmax<<<B_ * NH, 64>>>(temp, inv);
    // 5) W_eff = W_proj . blockdiag(A) -> fp16
    weff_kernel<<<B_ * NH, 256>>>(w_proj, We0);
    // 6) out = W_eff[b] @ (Vh + Vl)
    gemm_h2<<<dim3(C_ / 128, HW / 256, B_), 256, GSMEM>>>(
        We0, (size_t)C_ * C_, T0, T1, out, (size_t)C_ * HW);
}

// round 11
// speedup vs baseline: 2.2660x; 1.3220x over previous
#include <cuda_runtime.h>
#include <cuda.h>
#include <cuda_fp16.h>
#include <math.h>
#include <stdint.h>

// Problem constants (fixed shapes)
#define B_   16
#define C_   384
#define C3   1152
#define HW   4096
#define NH   8
#define DH   48
#define NCH  8
#define CHUNK 512
#define EPSN 1e-12f
#define KTOT 384

// GEMM smem geometry: block 128(M) x 256(N) x 32(K), 4-stage cp.async
// per stage: A fp16 [m128][k32+8pad] | B fp16 [k32][n256+8pad]
#define LDA 40
#define LDB 264
#define A_SZ   (128 * LDA * 2)            // 10240
#define B_SZ   (32 * LDB * 2)             // 16896
#define B_OFF  A_SZ                       // 10240
#define SST    (B_OFF + B_SZ)             // 27136
#define NSTG   4
#define GSMEM  (NSTG * SST)               // 108544

// ---------------- scratch (__device__ globals; no runtime alloc) -----------
__device__ __align__(128) float g_qkv[(size_t)B_ * C3 * HW];        // 302 MB
__device__ float g_inv[B_ * 2 * C_];
__device__ float g_Spart[NCH][B_ * NH][DH * DH];
__device__ float g_S[B_ * NH][DH * DH];
__device__ __align__(128) __half g_W0[C3 * C_];                     // Wh [m][k]
__device__ __align__(128) __half g_T0[(size_t)B_ * C_ * HW];        // X/V fp16 [k][n]
__device__ __align__(128) __half g_We0[B_ * C_ * C_];               // Weh [m][k]

// ---------------- PTX helpers ----------------------------------------------
__device__ __forceinline__ uint32_t smem_u32(const void* p) {
    uint32_t a;
    asm("{ .reg .u64 t; cvta.to.shared.u64 t, %1; cvt.u32.u64 %0, t; }"
        : "=r"(a) : "l"(p));
    return a;
}
__device__ __forceinline__ void ldm_x4(uint32_t* r, uint32_t addr) {
    asm volatile("ldmatrix.sync.aligned.m8n8.x4.shared.b16 {%0,%1,%2,%3}, [%4];"
        : "=r"(r[0]), "=r"(r[1]), "=r"(r[2]), "=r"(r[3]) : "r"(addr));
}
__device__ __forceinline__ void ldm_x4_t(uint32_t* r, uint32_t addr) {
    asm volatile("ldmatrix.sync.aligned.m8n8.x4.trans.shared.b16 {%0,%1,%2,%3}, [%4];"
        : "=r"(r[0]), "=r"(r[1]), "=r"(r[2]), "=r"(r[3]) : "r"(addr));
}
__device__ __forceinline__ void mma_h(float* c, const uint32_t* a,
                                      uint32_t b0, uint32_t b1) {
    asm volatile(
        "mma.sync.aligned.m16n8k16.row.col.f32.f16.f16.f32 "
        "{%0,%1,%2,%3}, {%4,%5,%6,%7}, {%8,%9}, {%0,%1,%2,%3};"
        : "+f"(c[0]), "+f"(c[1]), "+f"(c[2]), "+f"(c[3])
        : "r"(a[0]), "r"(a[1]), "r"(a[2]), "r"(a[3]), "r"(b0), "r"(b1));
}
__device__ __forceinline__ void cpa16(uint32_t s, const void* g) {
    asm volatile("cp.async.cg.shared.global [%0], [%1], 16;" :: "r"(s), "l"(g));
}
__device__ __forceinline__ void cpa_commit() {
    asm volatile("cp.async.commit_group;");
}
template <int N> __device__ __forceinline__ void cpa_wait() {
    asm volatile("cp.async.wait_group %0;" :: "n"(N));
}

// ---------------------------------------------------------------------------
// fp16 single-term GEMM: C[b][M,4096] = A[M,384] @ B[384,4096], both fp16.
// A [m][k]; B [k][n]. Block 128x256x32, 8 warps (2Mx4N), warp 64x64,
// 4-stage cp.async. grid (x = M/128, y = 4096/256, z = batch).
// ---------------------------------------------------------------------------
__global__ __launch_bounds__(256, 1)
void gemm_h1(const __half* __restrict__ Ahg, size_t aBatch,
             const __half* __restrict__ Bg,
             float* __restrict__ Cg, size_t cBatch)
{
    extern __shared__ char smem[];
    const uint32_t sbase = smem_u32(smem);

    const int t    = threadIdx.x;
    const int lane = t & 31;
    const int wid  = t >> 5;
    const int b    = blockIdx.z;
    const int m0   = blockIdx.x * 128;
    const int n0   = blockIdx.y * 256;
    const int warpM = (wid >> 2) * 64;
    const int warpN = (wid & 3) * 64;

    const __half* Asrc = Ahg + (size_t)b * aBatch + (size_t)m0 * KTOT;
    const __half* Bsrc = Bg + (size_t)b * C_ * HW;
    float* Cp = Cg + (size_t)b * cBatch;

    const int g  = lane >> 3;
    const int lr = lane & 7;
    const uint32_t aLane = (uint32_t)(((g & 1) * 8 + lr) * LDA + (g >> 1) * 8) * 2;
    const uint32_t bLane = (uint32_t)(((g & 1) * 8 + lr) * LDB + (g >> 1) * 8) * 2;

    float acc[4][8][4];
#pragma unroll
    for (int i = 0; i < 4; i++)
#pragma unroll
        for (int j = 0; j < 8; j++)
#pragma unroll
            for (int e = 0; e < 4; e++) acc[i][j][e] = 0.f;

    auto load_stage = [&](int kt, int stg) {
        const uint32_t sb = sbase + stg * SST;
#pragma unroll
        for (int it = 0; it < 2; it++) {          // A: 512 x 16B
            int c = t + it * 256;
            int r = c >> 2, kc = c & 3;
            cpa16(sb + r * (LDA * 2) + kc * 16,
                  Asrc + (size_t)r * KTOT + kt * 32 + kc * 8);
        }
#pragma unroll
        for (int it = 0; it < 4; it++) {          // B: 1024 x 16B
            int c = t + it * 256;
            int r = c >> 5, nc = c & 31;
            cpa16(sb + B_OFF + r * (LDB * 2) + nc * 16,
                  Bsrc + (size_t)(kt * 32 + r) * HW + n0 + nc * 8);
        }
        cpa_commit();
    };

    const int KT = KTOT / 32;   // 12
    load_stage(0, 0);
    load_stage(1, 1);
    load_stage(2, 2);

    for (int kt = 0; kt < KT; kt++) {
        if (kt + 3 < KT) load_stage(kt + 3, (kt + 3) % NSTG);
        if (kt + 3 < KT)      cpa_wait<3>();
        else if (kt + 2 < KT) cpa_wait<2>();
        else if (kt + 1 < KT) cpa_wait<1>();
        else                  cpa_wait<0>();
        __syncthreads();

        const uint32_t sb = sbase + (kt % NSTG) * SST;
#pragma unroll
        for (int k16 = 0; k16 < 2; k16++) {
            uint32_t Ah[4][4];
#pragma unroll
            for (int i = 0; i < 4; i++)
                ldm_x4(Ah[i], sb + aLane
                              + (uint32_t)((warpM + i * 16) * LDA + k16 * 16) * 2);
            uint32_t Bf[8][2];
#pragma unroll
            for (int p = 0; p < 4; p++) {
                uint32_t r[4];
                uint32_t bo = sb + B_OFF + bLane
                            + (uint32_t)(k16 * 16 * LDB + warpN + p * 16) * 2;
                ldm_x4_t(r, bo);
                Bf[p * 2][0] = r[0]; Bf[p * 2][1] = r[1];
                Bf[p * 2 + 1][0] = r[2]; Bf[p * 2 + 1][1] = r[3];
            }
#pragma unroll
            for (int i = 0; i < 4; i++)
#pragma unroll
                for (int j = 0; j < 8; j++)
                    mma_h(acc[i][j], Ah[i], Bf[j][0], Bf[j][1]);
        }
        __syncthreads();
    }

    const int erow = lane >> 2;
    const int ecol = (lane & 3) * 2;
#pragma unroll
    for (int i = 0; i < 4; i++)
#pragma unroll
        for (int j = 0; j < 8; j++) {
            float* base = Cp + (size_t)(m0 + warpM + i * 16 + erow) * HW
                             + n0 + warpN + j * 8 + ecol;
            *(float2*)base = make_float2(acc[i][j][0], acc[i][j][1]);
            *(float2*)(base + 8 * HW) = make_float2(acc[i][j][2], acc[i][j][3]);
        }
}

// ---------------------------------------------------------------------------
// fp32 -> fp16 convert (W, scalar grid-stride)
// ---------------------------------------------------------------------------
__global__ void wconvert(const float* __restrict__ src,
                         __half* __restrict__ dh, int n)
{
    int i = blockIdx.x * blockDim.x + threadIdx.x;
    if (i < n) dh[i] = __float2half(src[i]);
}

// ---------------------------------------------------------------------------
// fp32 -> fp16 convert, vectorized (X)
// ---------------------------------------------------------------------------
__global__ __launch_bounds__(256)
void xconv(const float* __restrict__ src, __half* __restrict__ d0, int n4)
{
    int i = blockIdx.x * 256 + threadIdx.x;
    if (i >= n4) return;
    float4 v = ((const float4*)src)[i];
    __half h0 = __float2half(v.x), h1 = __float2half(v.y);
    __half h2 = __float2half(v.z), h3 = __float2half(v.w);
    uint2 hp = make_uint2(
        (uint32_t)__half_as_ushort(h0) | ((uint32_t)__half_as_ushort(h1) << 16),
        (uint32_t)__half_as_ushort(h2) | ((uint32_t)__half_as_ushort(h3) << 16));
    ((uint2*)d0)[i] = hp;
}

// ---------------------------------------------------------------------------
// Depthwise 3x3 SAME conv, row-pair stencil. q/k fp32 in-place + fused norms;
// v -> fp16 plane.
// ---------------------------------------------------------------------------
__global__ __launch_bounds__(256)
void dwconv3x3(float* __restrict__ qkv, const float* __restrict__ wdw,
               float* __restrict__ inv, __half* __restrict__ V0)
{
    const int plane = blockIdx.x;
    const int b     = plane / C3;
    const int ch    = plane % C3;
    float* p = qkv + (size_t)plane * HW;

    __shared__ float s[66][72];
    const int t = threadIdx.x;

    if (t < 72)       { s[0][t] = 0.f; s[65][t] = 0.f; }
    else if (t < 136) { s[t - 72 + 1][3]  = 0.f; }
    else if (t < 200) { s[t - 136 + 1][68] = 0.f; }
#pragma unroll
    for (int it = 0; it < 4; it++) {
        int i = t + it * 256;
        int y = i >> 4, x4 = (i & 15) * 4;
        float4 v = *(const float4*)&p[y * 64 + x4];
        *(float4*)&s[y + 1][x4 + 4] = v;
    }

    float w[9];
#pragma unroll
    for (int j = 0; j < 9; j++) w[j] = wdw[ch * 9 + j];
    __syncthreads();

    const bool isv = (ch >= 2 * C_);
    __half* v0 = 0;
    if (isv) v0 = V0 + ((size_t)b * C_ + (ch - 2 * C_)) * HW;

    const int y  = (t >> 3) * 2;
    const int x8 = (t & 7) * 8;

    float v[4][16];
#pragma unroll
    for (int r = 0; r < 4; r++) {
        *(float4*)&v[r][0]  = *(float4*)&s[y + r][x8];
        *(float4*)&v[r][4]  = *(float4*)&s[y + r][x8 + 4];
        *(float4*)&v[r][8]  = *(float4*)&s[y + r][x8 + 8];
        *(float4*)&v[r][12] = *(float4*)&s[y + r][x8 + 12];
    }

    float o[2][8];
#pragma unroll
    for (int rr = 0; rr < 2; rr++)
#pragma unroll
        for (int j = 0; j < 8; j++) {
            float a = 0.f;
#pragma unroll
            for (int dy = 0; dy < 3; dy++)
#pragma unroll
                for (int dx = 0; dx < 3; dx++)
                    a = fmaf(v[rr + dy][3 + j + dx], w[dy * 3 + dx], a);
            o[rr][j] = a;
        }

    float ss = 0.f;
    if (!isv) {
#pragma unroll
        for (int rr = 0; rr < 2; rr++) {
            *(float4*)&p[(y + rr) * 64 + x8]     = make_float4(o[rr][0], o[rr][1], o[rr][2], o[rr][3]);
            *(float4*)&p[(y + rr) * 64 + x8 + 4] = make_float4(o[rr][4], o[rr][5], o[rr][6], o[rr][7]);
#pragma unroll
            for (int j = 0; j < 8; j++) ss = fmaf(o[rr][j], o[rr][j], ss);
        }
    } else {
#pragma unroll
        for (int rr = 0; rr < 2; rr++) {
            uint32_t hp[4];
#pragma unroll
            for (int j = 0; j < 4; j++) {
                __half ha = __float2half(o[rr][2 * j]);
                __half hb = __float2half(o[rr][2 * j + 1]);
                hp[j] = (uint32_t)__half_as_ushort(ha) |
                        ((uint32_t)__half_as_ushort(hb) << 16);
            }
            *(uint4*)&v0[(y + rr) * 64 + x8] = make_uint4(hp[0], hp[1], hp[2], hp[3]);
        }
    }

    if (ch < 2 * C_) {
        for (int off = 16; off > 0; off >>= 1)
            ss += __shfl_down_sync(0xffffffffu, ss, off);
        __shared__ float red[8];
        if ((t & 31) == 0) red[t >> 5] = ss;
        __syncthreads();
        if (t == 0) {
            float tot = 0.f;
#pragma unroll
            for (int i = 0; i < 8; i++) tot += red[i];
            inv[b * 2 * C_ + ch] = 1.f / fmaxf(sqrtf(tot), EPSN);
        }
    }
}

// ---------------------------------------------------------------------------
// Attention scores split-K partials (unnormalized Gram; aligned smem rows)
// ---------------------------------------------------------------------------
__global__ __launch_bounds__(256)
void attn_scores(const float* __restrict__ qkv)
{
    const int bh    = blockIdx.y;
    const int b     = bh >> 3;
    const int h     = bh & 7;
    const int chunk = blockIdx.x;
    const int t  = threadIdx.x;
    const int tx = t & 15;
    const int ty = t >> 4;

    const float* qbase = qkv + ((size_t)b * C3 + h * DH) * HW;
    const float* kbase = qbase + (size_t)C_ * HW;

    __shared__ float Qs[DH][68];
    __shared__ float Ks[DH][68];

    float acc[3][3];
#pragma unroll
    for (int i = 0; i < 3; i++)
#pragma unroll
        for (int j = 0; j < 3; j++) acc[i][j] = 0.f;

    const int kb = chunk * CHUNK;
    for (int k0 = 0; k0 < CHUNK; k0 += 64) {
        for (int i = t; i < DH * 16; i += 256) {
            int r  = i >> 4;
            int c4 = (i & 15) * 4;
            *(float4*)&Qs[r][c4] = *(const float4*)&qbase[(size_t)r * HW + kb + k0 + c4];
            *(float4*)&Ks[r][c4] = *(const float4*)&kbase[(size_t)r * HW + kb + k0 + c4];
        }
        __syncthreads();

#pragma unroll 16
        for (int kk = 0; kk < 64; kk++) {
            float q0 = Qs[ty     ][kk];
            float q1 = Qs[ty + 16][kk];
            float q2 = Qs[ty + 32][kk];
            float b0 = Ks[tx     ][kk];
            float b1 = Ks[tx + 16][kk];
            float b2 = Ks[tx + 32][kk];
            acc[0][0] = fmaf(q0, b0, acc[0][0]);
            acc[0][1] = fmaf(q0, b1, acc[0][1]);
            acc[0][2] = fmaf(q0, b2, acc[0][2]);
            acc[1][0] = fmaf(q1, b0, acc[1][0]);
            acc[1][1] = fmaf(q1, b1, acc[1][1]);
            acc[1][2] = fmaf(q1, b2, acc[1][2]);
            acc[2][0] = fmaf(q2, b0, acc[2][0]);
            acc[2][1] = fmaf(q2, b1, acc[2][1]);
            acc[2][2] = fmaf(q2, b2, acc[2][2]);
        }
        __syncthreads();
    }

    float* sp = &g_Spart[chunk][bh][0];
#pragma unroll
    for (int i = 0; i < 3; i++)
#pragma unroll
        for (int j = 0; j < 3; j++)
            sp[(ty + 16 * i) * DH + tx + 16 * j] = acc[i][j];
}

// reduce partials, apply rank-1 norm scaling + temperature, row softmax
__global__ __launch_bounds__(64)
void attn_softmax(const float* __restrict__ temp, const float* __restrict__ inv)
{
    const int bh = blockIdx.x;
    const int b  = bh >> 3;
    const int h  = bh & 7;
    const int r  = threadIdx.x;
    if (r >= DH) return;
    const float* ivq = inv + b * 2 * C_ + h * DH;
    const float* ivk = ivq + C_;
    const float rowscale = ivq[r] * temp[h];

    float vals[DH];
#pragma unroll
    for (int c = 0; c < DH; c++) {
        float s = 0.f;
#pragma unroll
        for (int ch = 0; ch < NCH; ch++)
            s += g_Spart[ch][bh][r * DH + c];
        vals[c] = s * rowscale * ivk[c];
    }
    float m = -INFINITY;
#pragma unroll
    for (int c = 0; c < DH; c++) m = fmaxf(m, vals[c]);
    float sum = 0.f;
#pragma unroll
    for (int c = 0; c < DH; c++) {
        vals[c] = expf(vals[c] - m);
        sum += vals[c];
    }
    float is = 1.f / sum;
#pragma unroll
    for (int c = 0; c < DH; c++)
        g_S[bh][r * DH + c] = vals[c] * is;
}

// ---------------------------------------------------------------------------
// W_eff[b] = W_proj @ blockdiag(A_soft[b]) ; fp16 plane. grid = B_*NH.
// ---------------------------------------------------------------------------
__global__ __launch_bounds__(256)
void weff_kernel(const float* __restrict__ wp, __half* __restrict__ eh)
{
    const int bh = blockIdx.x;
    const int b  = bh >> 3;
    const int h  = bh & 7;
    const int t  = threadIdx.x;

    __shared__ float As[DH][DH + 1];
    for (int i = t; i < DH * DH; i += 256)
        As[i / DH][i % DH] = g_S[bh][i];
    __syncthreads();

    for (int o = t; o < C_; o += 256) {
        float wrow[DH];
#pragma unroll
        for (int d = 0; d < DH; d++) wrow[d] = wp[(size_t)o * C_ + h * DH + d];
#pragma unroll 4
        for (int e = 0; e < DH; e++) {
            float acc = 0.f;
#pragma unroll
            for (int d = 0; d < DH; d++) acc = fmaf(wrow[d], As[d][e], acc);
            eh[((size_t)b * C_ + o) * C_ + h * DH + e] = __float2half(acc);
        }
    }
}

// ---------------------------------------------------------------------------
extern "C" void kernel_launch(void* const* d_in, const int* in_sizes, int n_in,
                              void* d_out, int out_size)
{
    const float* x      = (const float*)d_in[0];
    const float* w_qkv  = (const float*)d_in[1];
    const float* w_dw   = (const float*)d_in[2];
    const float* w_proj = (const float*)d_in[3];
    const float* temp   = (const float*)d_in[4];
    float* out = (float*)d_out;

    float *qkv, *inv;
    __half *W0, *T0, *We0;
    cudaGetSymbolAddress((void**)&qkv, g_qkv);
    cudaGetSymbolAddress((void**)&inv, g_inv);
    cudaGetSymbolAddress((void**)&W0, g_W0);
    cudaGetSymbolAddress((void**)&T0, g_T0);
    cudaGetSymbolAddress((void**)&We0, g_We0);

    cudaFuncSetAttribute(gemm_h1, cudaFuncAttributeMaxDynamicSharedMemorySize, GSMEM);

    // 1) W -> fp16 ; X -> fp16
    wconvert<<<(C3 * C_ + 255) / 256, 256>>>(w_qkv, W0, C3 * C_);
    xconv<<<(B_ * C_ * HW / 4 + 255) / 256, 256>>>(x, T0, B_ * C_ * HW / 4);
    // 2) qkv = W_qkv @ X  (single-term fp16)
    gemm_h1<<<dim3(C3 / 128, HW / 256, B_), 256, GSMEM>>>(
        W0, 0, T0, qkv, (size_t)C3 * HW);
    // 3) dwconv: q/k fp32 in-place + norms; v -> fp16 plane
    dwconv3x3<<<B_ * C3, 256>>>(qkv, w_dw, inv, T0);
    // 4) attention scores (unnormalized Gram) + softmax (applies norms)
    attn_scores<<<dim3(NCH, B_ * NH), 256>>>(qkv);
    attn_softmax<<<B_ * NH, 64>>>(temp, inv);
    // 5) W_eff = W_proj . blockdiag(A) -> fp16
    weff_kernel<<<B_ * NH, 256>>>(w_proj, We0);
    // 6) out = W_eff[b] @ V  (single-term fp16)
    gemm_h1<<<dim3(C_ / 128, HW / 256, B_), 256, GSMEM>>>(
        We0, (size_t)C_ * C_, T0, out, (size_t)C_ * HW);
}

// round 12
// speedup vs baseline: 2.3628x; 1.0427x over previous
#include <cuda_runtime.h>
#include <cuda.h>
#include <cuda_fp16.h>
#include <math.h>
#include <stdint.h>

// Problem constants (fixed shapes)
#define B_   16
#define C_   384
#define C3   1152
#define HW   4096
#define NH   8
#define DH   48
#define NCH  8
#define CHUNK 512
#define EPSN 1e-12f
#define KTOT 384

// GEMM smem geometry: block 128(M) x 256(N) x 32(K), 4-stage cp.async
#define LDA 40
#define LDB 264
#define A_SZ   (128 * LDA * 2)            // 10240
#define B_SZ   (32 * LDB * 2)             // 16896
#define B_OFF  A_SZ
#define SST    (B_OFF + B_SZ)             // 27136
#define NSTG   4
#define GSMEM  (NSTG * SST)               // 108544

// ---------------- scratch (__device__ globals; no runtime alloc) -----------
__device__ __align__(128) __half g_qkv16[(size_t)B_ * C3 * HW];     // 151 MB
__device__ float g_inv[B_ * 2 * C_];
__device__ float g_Spart[NCH][B_ * NH][DH * DH];
__device__ float g_S[B_ * NH][DH * DH];
__device__ __align__(128) __half g_W0[C3 * C_];                     // Wh [m][k]
__device__ __align__(128) __half g_T0[(size_t)B_ * C_ * HW];        // X fp16 [k][n]
__device__ __align__(128) __half g_We0[B_ * C_ * C_];               // Weh [m][k]

// ---------------- PTX helpers ----------------------------------------------
__device__ __forceinline__ uint32_t smem_u32(const void* p) {
    uint32_t a;
    asm("{ .reg .u64 t; cvta.to.shared.u64 t, %1; cvt.u32.u64 %0, t; }"
        : "=r"(a) : "l"(p));
    return a;
}
__device__ __forceinline__ void ldm_x4(uint32_t* r, uint32_t addr) {
    asm volatile("ldmatrix.sync.aligned.m8n8.x4.shared.b16 {%0,%1,%2,%3}, [%4];"
        : "=r"(r[0]), "=r"(r[1]), "=r"(r[2]), "=r"(r[3]) : "r"(addr));
}
__device__ __forceinline__ void ldm_x4_t(uint32_t* r, uint32_t addr) {
    asm volatile("ldmatrix.sync.aligned.m8n8.x4.trans.shared.b16 {%0,%1,%2,%3}, [%4];"
        : "=r"(r[0]), "=r"(r[1]), "=r"(r[2]), "=r"(r[3]) : "r"(addr));
}
__device__ __forceinline__ void mma_h(float* c, const uint32_t* a,
                                      uint32_t b0, uint32_t b1) {
    asm volatile(
        "mma.sync.aligned.m16n8k16.row.col.f32.f16.f16.f32 "
        "{%0,%1,%2,%3}, {%4,%5,%6,%7}, {%8,%9}, {%0,%1,%2,%3};"
        : "+f"(c[0]), "+f"(c[1]), "+f"(c[2]), "+f"(c[3])
        : "r"(a[0]), "r"(a[1]), "r"(a[2]), "r"(a[3]), "r"(b0), "r"(b1));
}
__device__ __forceinline__ void cpa16(uint32_t s, const void* g) {
    asm volatile("cp.async.cg.shared.global [%0], [%1], 16;" :: "r"(s), "l"(g));
}
__device__ __forceinline__ void cpa_commit() {
    asm volatile("cp.async.commit_group;");
}
template <int N> __device__ __forceinline__ void cpa_wait() {
    asm volatile("cp.async.wait_group %0;" :: "n"(N));
}

// ---------------------------------------------------------------------------
// fp16 GEMM: C[b][M,4096] = A[M,384] @ B[384,4096].  A [m][k]; B [k][n].
// Block 128x256x32, 8 warps (2Mx4N), warp 64x64, 4-stage cp.async.
// outH=1 -> fp16 output; outH=0 -> fp32 output.
// ---------------------------------------------------------------------------
__global__ __launch_bounds__(256, 1)
void gemm_h1(const __half* __restrict__ Ahg, size_t aBatch,
             const __half* __restrict__ Bg, size_t bBatch,
             void* __restrict__ Cvoid, size_t cBatch, int outH)
{
    extern __shared__ char smem[];
    const uint32_t sbase = smem_u32(smem);

    const int t    = threadIdx.x;
    const int lane = t & 31;
    const int wid  = t >> 5;
    const int b    = blockIdx.z;
    const int m0   = blockIdx.x * 128;
    const int n0   = blockIdx.y * 256;
    const int warpM = (wid >> 2) * 64;
    const int warpN = (wid & 3) * 64;

    const __half* Asrc = Ahg + (size_t)b * aBatch + (size_t)m0 * KTOT;
    const __half* Bsrc = Bg + (size_t)b * bBatch;

    const int g  = lane >> 3;
    const int lr = lane & 7;
    const uint32_t aLane = (uint32_t)(((g & 1) * 8 + lr) * LDA + (g >> 1) * 8) * 2;
    const uint32_t bLane = (uint32_t)(((g & 1) * 8 + lr) * LDB + (g >> 1) * 8) * 2;

    float acc[4][8][4];
#pragma unroll
    for (int i = 0; i < 4; i++)
#pragma unroll
        for (int j = 0; j < 8; j++)
#pragma unroll
            for (int e = 0; e < 4; e++) acc[i][j][e] = 0.f;

    auto load_stage = [&](int kt, int stg) {
        const uint32_t sb = sbase + stg * SST;
#pragma unroll
        for (int it = 0; it < 2; it++) {          // A: 512 x 16B
            int c = t + it * 256;
            int r = c >> 2, kc = c & 3;
            cpa16(sb + r * (LDA * 2) + kc * 16,
                  Asrc + (size_t)r * KTOT + kt * 32 + kc * 8);
        }
#pragma unroll
        for (int it = 0; it < 4; it++) {          // B: 1024 x 16B
            int c = t + it * 256;
            int r = c >> 5, nc = c & 31;
            cpa16(sb + B_OFF + r * (LDB * 2) + nc * 16,
                  Bsrc + (size_t)(kt * 32 + r) * HW + n0 + nc * 8);
        }
        cpa_commit();
    };

    const int KT = KTOT / 32;   // 12
    load_stage(0, 0);
    load_stage(1, 1);
    load_stage(2, 2);

    for (int kt = 0; kt < KT; kt++) {
        if (kt + 3 < KT) load_stage(kt + 3, (kt + 3) % NSTG);
        if (kt + 3 < KT)      cpa_wait<3>();
        else if (kt + 2 < KT) cpa_wait<2>();
        else if (kt + 1 < KT) cpa_wait<1>();
        else                  cpa_wait<0>();
        __syncthreads();

        const uint32_t sb = sbase + (kt % NSTG) * SST;
#pragma unroll
        for (int k16 = 0; k16 < 2; k16++) {
            uint32_t Ah[4][4];
#pragma unroll
            for (int i = 0; i < 4; i++)
                ldm_x4(Ah[i], sb + aLane
                              + (uint32_t)((warpM + i * 16) * LDA + k16 * 16) * 2);
            uint32_t Bf[8][2];
#pragma unroll
            for (int p = 0; p < 4; p++) {
                uint32_t r[4];
                uint32_t bo = sb + B_OFF + bLane
                            + (uint32_t)(k16 * 16 * LDB + warpN + p * 16) * 2;
                ldm_x4_t(r, bo);
                Bf[p * 2][0] = r[0]; Bf[p * 2][1] = r[1];
                Bf[p * 2 + 1][0] = r[2]; Bf[p * 2 + 1][1] = r[3];
            }
#pragma unroll
            for (int i = 0; i < 4; i++)
#pragma unroll
                for (int j = 0; j < 8; j++)
                    mma_h(acc[i][j], Ah[i], Bf[j][0], Bf[j][1]);
        }
        __syncthreads();
    }

    const int erow = lane >> 2;
    const int ecol = (lane & 3) * 2;
    if (outH) {
        __half* Cp = (__half*)Cvoid + (size_t)b * cBatch;
#pragma unroll
        for (int i = 0; i < 4; i++)
#pragma unroll
            for (int j = 0; j < 8; j++) {
                __half* base = Cp + (size_t)(m0 + warpM + i * 16 + erow) * HW
                                  + n0 + warpN + j * 8 + ecol;
                __half2 v01 = __floats2half2_rn(acc[i][j][0], acc[i][j][1]);
                __half2 v23 = __floats2half2_rn(acc[i][j][2], acc[i][j][3]);
                *(__half2*)base = v01;
                *(__half2*)(base + 8 * HW) = v23;
            }
    } else {
        float* Cp = (float*)Cvoid + (size_t)b * cBatch;
#pragma unroll
        for (int i = 0; i < 4; i++)
#pragma unroll
            for (int j = 0; j < 8; j++) {
                float* base = Cp + (size_t)(m0 + warpM + i * 16 + erow) * HW
                                 + n0 + warpN + j * 8 + ecol;
                *(float2*)base = make_float2(acc[i][j][0], acc[i][j][1]);
                *(float2*)(base + 8 * HW) = make_float2(acc[i][j][2], acc[i][j][3]);
            }
    }
}

// ---------------------------------------------------------------------------
__global__ void wconvert(const float* __restrict__ src,
                         __half* __restrict__ dh, int n)
{
    int i = blockIdx.x * blockDim.x + threadIdx.x;
    if (i < n) dh[i] = __float2half(src[i]);
}

__global__ __launch_bounds__(256)
void xconv(const float* __restrict__ src, __half* __restrict__ d0, int n4)
{
    int i = blockIdx.x * 256 + threadIdx.x;
    if (i >= n4) return;
    float4 v = ((const float4*)src)[i];
    __half2 a = __floats2half2_rn(v.x, v.y);
    __half2 b = __floats2half2_rn(v.z, v.w);
    ((uint2*)d0)[i] = make_uint2(*(uint32_t*)&a, *(uint32_t*)&b);
}

// ---------------------------------------------------------------------------
// Depthwise 3x3 SAME conv on fp16 qkv, in place. Stencil in fp32.
// q/k channels also produce fused inv L2 norms.
// ---------------------------------------------------------------------------
__global__ __launch_bounds__(256)
void dwconv3x3(__half* __restrict__ qkv, const float* __restrict__ wdw,
               float* __restrict__ inv)
{
    const int plane = blockIdx.x;
    const int b     = plane / C3;
    const int ch    = plane % C3;
    __half* p = qkv + (size_t)plane * HW;

    __shared__ float s[66][72];
    const int t = threadIdx.x;

    if (t < 72)       { s[0][t] = 0.f; s[65][t] = 0.f; }
    else if (t < 136) { s[t - 72 + 1][3]  = 0.f; }
    else if (t < 200) { s[t - 136 + 1][68] = 0.f; }
#pragma unroll
    for (int it = 0; it < 2; it++) {
        int i = t + it * 256;                 // 512 chunks of 8 halves
        int y = i >> 3, x8 = (i & 7) * 8;
        uint4 raw = *(const uint4*)&p[y * 64 + x8];
        const __half2* hp = (const __half2*)&raw;
        float* d = &s[y + 1][x8 + 4];
        float2 f0 = __half22float2(hp[0]);
        float2 f1 = __half22float2(hp[1]);
        float2 f2 = __half22float2(hp[2]);
        float2 f3 = __half22float2(hp[3]);
        d[0] = f0.x; d[1] = f0.y; d[2] = f1.x; d[3] = f1.y;
        d[4] = f2.x; d[5] = f2.y; d[6] = f3.x; d[7] = f3.y;
    }

    float w[9];
#pragma unroll
    for (int j = 0; j < 9; j++) w[j] = wdw[ch * 9 + j];
    __syncthreads();

    const int y  = (t >> 3) * 2;
    const int x8 = (t & 7) * 8;

    float v[4][16];
#pragma unroll
    for (int r = 0; r < 4; r++) {
        *(float4*)&v[r][0]  = *(float4*)&s[y + r][x8];
        *(float4*)&v[r][4]  = *(float4*)&s[y + r][x8 + 4];
        *(float4*)&v[r][8]  = *(float4*)&s[y + r][x8 + 8];
        *(float4*)&v[r][12] = *(float4*)&s[y + r][x8 + 12];
    }

    float o[2][8];
#pragma unroll
    for (int rr = 0; rr < 2; rr++)
#pragma unroll
        for (int j = 0; j < 8; j++) {
            float a = 0.f;
#pragma unroll
            for (int dy = 0; dy < 3; dy++)
#pragma unroll
                for (int dx = 0; dx < 3; dx++)
                    a = fmaf(v[rr + dy][3 + j + dx], w[dy * 3 + dx], a);
            o[rr][j] = a;
        }

    float ss = 0.f;
#pragma unroll
    for (int rr = 0; rr < 2; rr++) {
        __half2 h0 = __floats2half2_rn(o[rr][0], o[rr][1]);
        __half2 h1 = __floats2half2_rn(o[rr][2], o[rr][3]);
        __half2 h2 = __floats2half2_rn(o[rr][4], o[rr][5]);
        __half2 h3 = __floats2half2_rn(o[rr][6], o[rr][7]);
        *(uint4*)&p[(y + rr) * 64 + x8] = make_uint4(
            *(uint32_t*)&h0, *(uint32_t*)&h1, *(uint32_t*)&h2, *(uint32_t*)&h3);
#pragma unroll
        for (int j = 0; j < 8; j++) ss = fmaf(o[rr][j], o[rr][j], ss);
    }

    if (ch < 2 * C_) {
        for (int off = 16; off > 0; off >>= 1)
            ss += __shfl_down_sync(0xffffffffu, ss, off);
        __shared__ float red[8];
        if ((t & 31) == 0) red[t >> 5] = ss;
        __syncthreads();
        if (t == 0) {
            float tot = 0.f;
#pragma unroll
            for (int i = 0; i < 8; i++) tot += red[i];
            inv[b * 2 * C_ + ch] = 1.f / fmaxf(sqrtf(tot), EPSN);
        }
    }
}

// ---------------------------------------------------------------------------
// Attention scores split-K partials on fp16 q/k (unnormalized Gram; fp32 acc)
// ---------------------------------------------------------------------------
__global__ __launch_bounds__(256)
void attn_scores(const __half* __restrict__ qkv)
{
    const int bh    = blockIdx.y;
    const int b     = bh >> 3;
    const int h     = bh & 7;
    const int chunk = blockIdx.x;
    const int t  = threadIdx.x;
    const int tx = t & 15;
    const int ty = t >> 4;

    const __half* qbase = qkv + ((size_t)b * C3 + h * DH) * HW;
    const __half* kbase = qbase + (size_t)C_ * HW;

    __shared__ float Qs[DH][68];
    __shared__ float Ks[DH][68];

    float acc[3][3];
#pragma unroll
    for (int i = 0; i < 3; i++)
#pragma unroll
        for (int j = 0; j < 3; j++) acc[i][j] = 0.f;

    const int kb = chunk * CHUNK;
    for (int k0 = 0; k0 < CHUNK; k0 += 64) {
        for (int i = t; i < DH * 8; i += 256) {
            int r  = i >> 3;
            int c8 = (i & 7) * 8;
            uint4 qr = *(const uint4*)&qbase[(size_t)r * HW + kb + k0 + c8];
            uint4 kr = *(const uint4*)&kbase[(size_t)r * HW + kb + k0 + c8];
            const __half2* qh = (const __half2*)&qr;
            const __half2* kh = (const __half2*)&kr;
#pragma unroll
            for (int u = 0; u < 4; u++) {
                float2 qf = __half22float2(qh[u]);
                float2 kf = __half22float2(kh[u]);
                Qs[r][c8 + 2 * u]     = qf.x;
                Qs[r][c8 + 2 * u + 1] = qf.y;
                Ks[r][c8 + 2 * u]     = kf.x;
                Ks[r][c8 + 2 * u + 1] = kf.y;
            }
        }
        __syncthreads();

#pragma unroll 16
        for (int kk = 0; kk < 64; kk++) {
            float q0 = Qs[ty     ][kk];
            float q1 = Qs[ty + 16][kk];
            float q2 = Qs[ty + 32][kk];
            float b0 = Ks[tx     ][kk];
            float b1 = Ks[tx + 16][kk];
            float b2 = Ks[tx + 32][kk];
            acc[0][0] = fmaf(q0, b0, acc[0][0]);
            acc[0][1] = fmaf(q0, b1, acc[0][1]);
            acc[0][2] = fmaf(q0, b2, acc[0][2]);
            acc[1][0] = fmaf(q1, b0, acc[1][0]);
            acc[1][1] = fmaf(q1, b1, acc[1][1]);
            acc[1][2] = fmaf(q1, b2, acc[1][2]);
            acc[2][0] = fmaf(q2, b0, acc[2][0]);
            acc[2][1] = fmaf(q2, b1, acc[2][1]);
            acc[2][2] = fmaf(q2, b2, acc[2][2]);
        }
        __syncthreads();
    }

    float* sp = &g_Spart[chunk][bh][0];
#pragma unroll
    for (int i = 0; i < 3; i++)
#pragma unroll
        for (int j = 0; j < 3; j++)
            sp[(ty + 16 * i) * DH + tx + 16 * j] = acc[i][j];
}

// reduce partials, apply rank-1 norm scaling + temperature, row softmax
__global__ __launch_bounds__(64)
void attn_softmax(const float* __restrict__ temp, const float* __restrict__ inv)
{
    const int bh = blockIdx.x;
    const int b  = bh >> 3;
    const int h  = bh & 7;
    const int r  = threadIdx.x;
    if (r >= DH) return;
    const float* ivq = inv + b * 2 * C_ + h * DH;
    const float* ivk = ivq + C_;
    const float rowscale = ivq[r] * temp[h];

    float vals[DH];
#pragma unroll
    for (int c = 0; c < DH; c++) {
        float s = 0.f;
#pragma unroll
        for (int ch = 0; ch < NCH; ch++)
            s += g_Spart[ch][bh][r * DH + c];
        vals[c] = s * rowscale * ivk[c];
    }
    float m = -INFINITY;
#pragma unroll
    for (int c = 0; c < DH; c++) m = fmaxf(m, vals[c]);
    float sum = 0.f;
#pragma unroll
    for (int c = 0; c < DH; c++) {
        vals[c] = expf(vals[c] - m);
        sum += vals[c];
    }
    float is = 1.f / sum;
#pragma unroll
    for (int c = 0; c < DH; c++)
        g_S[bh][r * DH + c] = vals[c] * is;
}

// ---------------------------------------------------------------------------
// W_eff[b] = W_proj @ blockdiag(A_soft[b]) -> fp16. grid = B_*NH.
// ---------------------------------------------------------------------------
__global__ __launch_bounds__(256)
void weff_kernel(const float* __restrict__ wp, __half* __restrict__ eh)
{
    const int bh = blockIdx.x;
    const int b  = bh >> 3;
    const int h  = bh & 7;
    const int t  = threadIdx.x;

    __shared__ float As[DH][DH + 1];
    for (int i = t; i < DH * DH; i += 256)
        As[i / DH][i % DH] = g_S[bh][i];
    __syncthreads();

    for (int o = t; o < C_; o += 256) {
        float wrow[DH];
#pragma unroll
        for (int d = 0; d < DH; d++) wrow[d] = wp[(size_t)o * C_ + h * DH + d];
#pragma unroll 4
        for (int e = 0; e < DH; e++) {
            float acc = 0.f;
#pragma unroll
            for (int d = 0; d < DH; d++) acc = fmaf(wrow[d], As[d][e], acc);
            eh[((size_t)b * C_ + o) * C_ + h * DH + e] = __float2half(acc);
        }
    }
}

// ---------------------------------------------------------------------------
extern "C" void kernel_launch(void* const* d_in, const int* in_sizes, int n_in,
                              void* d_out, int out_size)
{
    const float* x      = (const float*)d_in[0];
    const float* w_qkv  = (const float*)d_in[1];
    const float* w_dw   = (const float*)d_in[2];
    const float* w_proj = (const float*)d_in[3];
    const float* temp   = (const float*)d_in[4];
    float* out = (float*)d_out;

    float* inv;
    __half *qkv16, *W0, *T0, *We0;
    cudaGetSymbolAddress((void**)&qkv16, g_qkv16);
    cudaGetSymbolAddress((void**)&inv, g_inv);
    cudaGetSymbolAddress((void**)&W0, g_W0);
    cudaGetSymbolAddress((void**)&T0, g_T0);
    cudaGetSymbolAddress((void**)&We0, g_We0);

    cudaFuncSetAttribute(gemm_h1, cudaFuncAttributeMaxDynamicSharedMemorySize, GSMEM);

    // 1) W -> fp16 ; X -> fp16
    wconvert<<<(C3 * C_ + 255) / 256, 256>>>(w_qkv, W0, C3 * C_);
    xconv<<<(B_ * C_ * HW / 4 + 255) / 256, 256>>>(x, T0, B_ * C_ * HW / 4);
    // 2) qkv16 = W_qkv @ X  (fp16 output)
    gemm_h1<<<dim3(C3 / 128, HW / 256, B_), 256, GSMEM>>>(
        W0, 0, T0, (size_t)C_ * HW, qkv16, (size_t)C3 * HW, 1);
    // 3) dwconv in place on fp16 qkv + fused q/k norms
    dwconv3x3<<<B_ * C3, 256>>>(qkv16, w_dw, inv);
    // 4) attention scores (fp16 q/k, unnormalized Gram) + softmax
    attn_scores<<<dim3(NCH, B_ * NH), 256>>>(qkv16);
    attn_softmax<<<B_ * NH, 64>>>(temp, inv);
    // 5) W_eff = W_proj . blockdiag(A) -> fp16
    weff_kernel<<<B_ * NH, 256>>>(w_proj, We0);
    // 6) out = W_eff[b] @ V  (V = fp16 v-plane inside qkv16; fp32 output)
    gemm_h1<<<dim3(C_ / 128, HW / 256, B_), 256, GSMEM>>>(
        We0, (size_t)C_ * C_, qkv16 + (size_t)2 * C_ * HW, (size_t)C3 * HW,
        out, (size_t)C_ * HW, 0);
}

// round 13
// speedup vs baseline: 2.8136x; 1.1908x over previous
#include <cuda_runtime.h>
#include <cuda.h>
#include <cuda_fp16.h>
#include <math.h>
#include <stdint.h>

// Problem constants (fixed shapes)
#define B_   16
#define C_   384
#define C3   1152
#define HW   4096
#define NH   8
#define DH   48
#define NCH  8
#define CHUNK 512
#define EPSN 1e-12f
#define KTOT 384

// GEMM smem geometry: block 128(M) x 256(N) x 32(K), 4-stage cp.async
#define LDA 40
#define LDB 264
#define A_SZ   (128 * LDA * 2)            // 10240
#define B_SZ   (32 * LDB * 2)             // 16896
#define B_OFF  A_SZ
#define SST    (B_OFF + B_SZ)             // 27136
#define NSTG   4
#define GSMEM  (NSTG * SST)               // 108544

// ---------------- scratch (__device__ globals; no runtime alloc) -----------
__device__ __align__(128) __half g_qkv16[(size_t)B_ * C3 * HW];     // 151 MB
__device__ float g_inv[B_ * 2 * C_];
__device__ float g_Spart[NCH][B_ * NH][DH * DH];
__device__ float g_S[B_ * NH][DH * DH];
__device__ __align__(128) __half g_W0[C3 * C_];                     // Wh [m][k]
__device__ __align__(128) __half g_T0[(size_t)B_ * C_ * HW];        // X fp16 [k][n]
__device__ __align__(128) __half g_We0[B_ * C_ * C_];               // Weh [m][k]

// ---------------- PTX helpers ----------------------------------------------
__device__ __forceinline__ uint32_t smem_u32(const void* p) {
    uint32_t a;
    asm("{ .reg .u64 t; cvta.to.shared.u64 t, %1; cvt.u32.u64 %0, t; }"
        : "=r"(a) : "l"(p));
    return a;
}
__device__ __forceinline__ void ldm_x4(uint32_t* r, uint32_t addr) {
    asm volatile("ldmatrix.sync.aligned.m8n8.x4.shared.b16 {%0,%1,%2,%3}, [%4];"
        : "=r"(r[0]), "=r"(r[1]), "=r"(r[2]), "=r"(r[3]) : "r"(addr));
}
__device__ __forceinline__ void ldm_x4_t(uint32_t* r, uint32_t addr) {
    asm volatile("ldmatrix.sync.aligned.m8n8.x4.trans.shared.b16 {%0,%1,%2,%3}, [%4];"
        : "=r"(r[0]), "=r"(r[1]), "=r"(r[2]), "=r"(r[3]) : "r"(addr));
}
__device__ __forceinline__ void mma_h(float* c, const uint32_t* a,
                                      uint32_t b0, uint32_t b1) {
    asm volatile(
        "mma.sync.aligned.m16n8k16.row.col.f32.f16.f16.f32 "
        "{%0,%1,%2,%3}, {%4,%5,%6,%7}, {%8,%9}, {%0,%1,%2,%3};"
        : "+f"(c[0]), "+f"(c[1]), "+f"(c[2]), "+f"(c[3])
        : "r"(a[0]), "r"(a[1]), "r"(a[2]), "r"(a[3]), "r"(b0), "r"(b1));
}
__device__ __forceinline__ void cpa16(uint32_t s, const void* g) {
    asm volatile("cp.async.cg.shared.global [%0], [%1], 16;" :: "r"(s), "l"(g));
}
__device__ __forceinline__ void cpa_commit() {
    asm volatile("cp.async.commit_group;");
}
template <int N> __device__ __forceinline__ void cpa_wait() {
    asm volatile("cp.async.wait_group %0;" :: "n"(N));
}

// ---------------------------------------------------------------------------
// fp16 GEMM: C[b][M,4096] = A[M,384] @ B[384,4096].  A [m][k]; B [k][n].
// Block 128x256x32, 8 warps (2Mx4N), warp 64x64, 4-stage cp.async.
// outH=1 -> fp16 output; outH=0 -> fp32 output.
// ---------------------------------------------------------------------------
__global__ __launch_bounds__(256, 1)
void gemm_h1(const __half* __restrict__ Ahg, size_t aBatch,
             const __half* __restrict__ Bg, size_t bBatch,
             void* __restrict__ Cvoid, size_t cBatch, int outH)
{
    extern __shared__ char smem[];
    const uint32_t sbase = smem_u32(smem);

    const int t    = threadIdx.x;
    const int lane = t & 31;
    const int wid  = t >> 5;
    const int b    = blockIdx.z;
    const int m0   = blockIdx.x * 128;
    const int n0   = blockIdx.y * 256;
    const int warpM = (wid >> 2) * 64;
    const int warpN = (wid & 3) * 64;

    const __half* Asrc = Ahg + (size_t)b * aBatch + (size_t)m0 * KTOT;
    const __half* Bsrc = Bg + (size_t)b * bBatch;

    const int g  = lane >> 3;
    const int lr = lane & 7;
    const uint32_t aLane = (uint32_t)(((g & 1) * 8 + lr) * LDA + (g >> 1) * 8) * 2;
    const uint32_t bLane = (uint32_t)(((g & 1) * 8 + lr) * LDB + (g >> 1) * 8) * 2;

    float acc[4][8][4];
#pragma unroll
    for (int i = 0; i < 4; i++)
#pragma unroll
        for (int j = 0; j < 8; j++)
#pragma unroll
            for (int e = 0; e < 4; e++) acc[i][j][e] = 0.f;

    auto load_stage = [&](int kt, int stg) {
        const uint32_t sb = sbase + stg * SST;
#pragma unroll
        for (int it = 0; it < 2; it++) {          // A: 512 x 16B
            int c = t + it * 256;
            int r = c >> 2, kc = c & 3;
            cpa16(sb + r * (LDA * 2) + kc * 16,
                  Asrc + (size_t)r * KTOT + kt * 32 + kc * 8);
        }
#pragma unroll
        for (int it = 0; it < 4; it++) {          // B: 1024 x 16B
            int c = t + it * 256;
            int r = c >> 5, nc = c & 31;
            cpa16(sb + B_OFF + r * (LDB * 2) + nc * 16,
                  Bsrc + (size_t)(kt * 32 + r) * HW + n0 + nc * 8);
        }
        cpa_commit();
    };

    const int KT = KTOT / 32;   // 12
    load_stage(0, 0);
    load_stage(1, 1);
    load_stage(2, 2);

    for (int kt = 0; kt < KT; kt++) {
        if (kt + 3 < KT) load_stage(kt + 3, (kt + 3) % NSTG);
        if (kt + 3 < KT)      cpa_wait<3>();
        else if (kt + 2 < KT) cpa_wait<2>();
        else if (kt + 1 < KT) cpa_wait<1>();
        else                  cpa_wait<0>();
        __syncthreads();

        const uint32_t sb = sbase + (kt % NSTG) * SST;
#pragma unroll
        for (int k16 = 0; k16 < 2; k16++) {
            uint32_t Ah[4][4];
#pragma unroll
            for (int i = 0; i < 4; i++)
                ldm_x4(Ah[i], sb + aLane
                              + (uint32_t)((warpM + i * 16) * LDA + k16 * 16) * 2);
            uint32_t Bf[8][2];
#pragma unroll
            for (int p = 0; p < 4; p++) {
                uint32_t r[4];
                uint32_t bo = sb + B_OFF + bLane
                            + (uint32_t)(k16 * 16 * LDB + warpN + p * 16) * 2;
                ldm_x4_t(r, bo);
                Bf[p * 2][0] = r[0]; Bf[p * 2][1] = r[1];
                Bf[p * 2 + 1][0] = r[2]; Bf[p * 2 + 1][1] = r[3];
            }
#pragma unroll
            for (int i = 0; i < 4; i++)
#pragma unroll
                for (int j = 0; j < 8; j++)
                    mma_h(acc[i][j], Ah[i], Bf[j][0], Bf[j][1]);
        }
        __syncthreads();
    }

    const int erow = lane >> 2;
    const int ecol = (lane & 3) * 2;
    if (outH) {
        __half* Cp = (__half*)Cvoid + (size_t)b * cBatch;
#pragma unroll
        for (int i = 0; i < 4; i++)
#pragma unroll
            for (int j = 0; j < 8; j++) {
                __half* base = Cp + (size_t)(m0 + warpM + i * 16 + erow) * HW
                                  + n0 + warpN + j * 8 + ecol;
                __half2 v01 = __floats2half2_rn(acc[i][j][0], acc[i][j][1]);
                __half2 v23 = __floats2half2_rn(acc[i][j][2], acc[i][j][3]);
                *(__half2*)base = v01;
                *(__half2*)(base + 8 * HW) = v23;
            }
    } else {
        float* Cp = (float*)Cvoid + (size_t)b * cBatch;
#pragma unroll
        for (int i = 0; i < 4; i++)
#pragma unroll
            for (int j = 0; j < 8; j++) {
                float* base = Cp + (size_t)(m0 + warpM + i * 16 + erow) * HW
                                 + n0 + warpN + j * 8 + ecol;
                *(float2*)base = make_float2(acc[i][j][0], acc[i][j][1]);
                *(float2*)(base + 8 * HW) = make_float2(acc[i][j][2], acc[i][j][3]);
            }
    }
}

// ---------------------------------------------------------------------------
__global__ void wconvert(const float* __restrict__ src,
                         __half* __restrict__ dh, int n)
{
    int i = blockIdx.x * blockDim.x + threadIdx.x;
    if (i < n) dh[i] = __float2half(src[i]);
}

__global__ __launch_bounds__(256)
void xconv(const float* __restrict__ src, __half* __restrict__ d0, int n4)
{
    int i = blockIdx.x * 256 + threadIdx.x;
    if (i >= n4) return;
    float4 v = ((const float4*)src)[i];
    __half2 a = __floats2half2_rn(v.x, v.y);
    __half2 b = __floats2half2_rn(v.z, v.w);
    ((uint2*)d0)[i] = make_uint2(*(uint32_t*)&a, *(uint32_t*)&b);
}

// ---------------------------------------------------------------------------
// Depthwise 3x3 SAME conv on fp16 qkv, in place. fp16 smem staging (halves
// LDS bytes); stencil math in fp32; fused q/k inv L2 norms.
// ---------------------------------------------------------------------------
__global__ __launch_bounds__(256)
void dwconv3x3(__half* __restrict__ qkv, const float* __restrict__ wdw,
               float* __restrict__ inv)
{
    const int plane = blockIdx.x;
    const int b     = plane / C3;
    const int ch    = plane % C3;
    __half* p = qkv + (size_t)plane * HW;

    __shared__ __align__(16) __half s[66][88];   // 176 B rows
    const int t = threadIdx.x;

    // zero everything (covers halo), then fill interior at col offset 8
    {
        uint4 z = make_uint4(0, 0, 0, 0);
        for (int i = t; i < 66 * 88 * 2 / 16; i += 256)
            ((uint4*)s)[i] = z;
    }
    __syncthreads();
#pragma unroll
    for (int it = 0; it < 2; it++) {
        int i = t + it * 256;                 // 512 chunks of 8 halves
        int y = i >> 3, x8 = (i & 7) * 8;
        *(uint4*)&s[y + 1][x8 + 8] = *(const uint4*)&p[y * 64 + x8];
    }

    float w[9];
#pragma unroll
    for (int j = 0; j < 9; j++) w[j] = wdw[ch * 9 + j];
    __syncthreads();

    const int y  = (t >> 3) * 2;
    const int x8 = (t & 7) * 8;

    // load 4 rows x 24 halves (3 uint4), convert window cols x8+6..x8+17
    float v[4][12];
#pragma unroll
    for (int r = 0; r < 4; r++) {
        uint4 u0 = *(uint4*)&s[y + r][x8];
        uint4 u1 = *(uint4*)&s[y + r][x8 + 8];
        uint4 u2 = *(uint4*)&s[y + r][x8 + 16];
        __half2 hh[12];
        *(uint4*)&hh[0] = u0;
        *(uint4*)&hh[4] = u1;
        *(uint4*)&hh[8] = u2;
        // halves index 6..17 -> half2 index 3..8
#pragma unroll
        for (int u = 0; u < 6; u++) {
            float2 f = __half22float2(hh[3 + u]);
            v[r][2 * u]     = f.x;
            v[r][2 * u + 1] = f.y;
        }
    }
    // v[r][idx]: idx u corresponds to smem col x8+6+u = global x8-2+u
    // output j (global x8+j) needs inputs global x8+j-1+dx -> idx j+dx+1... :
    // global x8+j-1+dx = x8-2 + (j+dx+1) -> idx = j+dx+1? check: dx=0 -> x8+j-1
    //   -> idx j+1-... x8-2+u = x8+j-1 -> u = j+1. dx range 0..2 -> u = j+1..j+3.
    float o[2][8];
#pragma unroll
    for (int rr = 0; rr < 2; rr++)
#pragma unroll
        for (int j = 0; j < 8; j++) {
            float a = 0.f;
#pragma unroll
            for (int dy = 0; dy < 3; dy++)
#pragma unroll
                for (int dx = 0; dx < 3; dx++)
                    a = fmaf(v[rr + dy][j + 1 + dx], w[dy * 3 + dx], a);
            o[rr][j] = a;
        }

    float ss = 0.f;
#pragma unroll
    for (int rr = 0; rr < 2; rr++) {
        __half2 h0 = __floats2half2_rn(o[rr][0], o[rr][1]);
        __half2 h1 = __floats2half2_rn(o[rr][2], o[rr][3]);
        __half2 h2 = __floats2half2_rn(o[rr][4], o[rr][5]);
        __half2 h3 = __floats2half2_rn(o[rr][6], o[rr][7]);
        *(uint4*)&p[(y + rr) * 64 + x8] = make_uint4(
            *(uint32_t*)&h0, *(uint32_t*)&h1, *(uint32_t*)&h2, *(uint32_t*)&h3);
#pragma unroll
        for (int j = 0; j < 8; j++) ss = fmaf(o[rr][j], o[rr][j], ss);
    }

    if (ch < 2 * C_) {
        for (int off = 16; off > 0; off >>= 1)
            ss += __shfl_down_sync(0xffffffffu, ss, off);
        __shared__ float red[8];
        if ((t & 31) == 0) red[t >> 5] = ss;
        __syncthreads();
        if (t == 0) {
            float tot = 0.f;
#pragma unroll
            for (int i = 0; i < 8; i++) tot += red[i];
            inv[b * 2 * C_ + ch] = 1.f / fmaxf(sqrtf(tot), EPSN);
        }
    }
}

// ---------------------------------------------------------------------------
// Attention scores via mma.sync: partial unnormalized Gram over one k-chunk.
// 96 threads (3 warps); warp w owns the n16 column w of the 48x48 tile
// (3 m16 x 2 n8 frags). q [m][k] plain-ldm; k [n][k] plain-ldm (R4 convention).
// ---------------------------------------------------------------------------
#define LDQ 72   // halves per smem row (144 B)
__global__ __launch_bounds__(96)
void attn_scores(const __half* __restrict__ qkv)
{
    const int bh    = blockIdx.y;
    const int b     = bh >> 3;
    const int h     = bh & 7;
    const int chunk = blockIdx.x;
    const int t    = threadIdx.x;
    const int lane = t & 31;
    const int wid  = t >> 5;     // 0..2 = n16 tile

    const __half* qbase = qkv + ((size_t)b * C3 + h * DH) * HW;
    const __half* kbase = qbase + (size_t)C_ * HW;

    __shared__ __align__(16) __half Qs[DH][LDQ];
    __shared__ __align__(16) __half Ks[DH][LDQ];
    const uint32_t qb = smem_u32(&Qs[0][0]);
    const uint32_t kb2 = smem_u32(&Ks[0][0]);

    const int g  = lane >> 3;
    const int lr = lane & 7;
    const uint32_t aLane = (uint32_t)(((g & 1) * 8 + lr) * LDQ + (g >> 1) * 8) * 2;
    const uint32_t bLane = (uint32_t)((wid * 16 + (g >> 1) * 8 + lr) * LDQ + (g & 1) * 8) * 2;

    float acc[3][2][4];
#pragma unroll
    for (int i = 0; i < 3; i++)
#pragma unroll
        for (int p = 0; p < 2; p++)
#pragma unroll
            for (int e = 0; e < 4; e++) acc[i][p][e] = 0.f;

    const int kb0 = chunk * CHUNK;
    for (int kt = 0; kt < CHUNK / 64; kt++) {       // 8 outer steps of k64
        for (int i = t; i < DH * 8; i += 96) {
            int r  = i >> 3;
            int c8 = (i & 7) * 8;
            *(uint4*)&Qs[r][c8] = *(const uint4*)&qbase[(size_t)r * HW + kb0 + kt * 64 + c8];
            *(uint4*)&Ks[r][c8] = *(const uint4*)&kbase[(size_t)r * HW + kb0 + kt * 64 + c8];
        }
        __syncthreads();

#pragma unroll
        for (int k16 = 0; k16 < 4; k16++) {
            uint32_t Aq[3][4];
#pragma unroll
            for (int i = 0; i < 3; i++)
                ldm_x4(Aq[i], qb + aLane + (uint32_t)(i * 16 * LDQ + k16 * 16) * 2);
            uint32_t r[4];
            ldm_x4(r, kb2 + bLane + (uint32_t)(k16 * 16) * 2);
#pragma unroll
            for (int i = 0; i < 3; i++) {
                mma_h(acc[i][0], Aq[i], r[0], r[1]);
                mma_h(acc[i][1], Aq[i], r[2], r[3]);
            }
        }
        __syncthreads();
    }

    const int erow = lane >> 2;
    const int ecol = (lane & 3) * 2;
    float* sp = &g_Spart[chunk][bh][0];
#pragma unroll
    for (int i = 0; i < 3; i++)
#pragma unroll
        for (int p = 0; p < 2; p++) {
            float* base = sp + (i * 16 + erow) * DH + wid * 16 + p * 8 + ecol;
            *(float2*)base = make_float2(acc[i][p][0], acc[i][p][1]);
            *(float2*)(base + 8 * DH) = make_float2(acc[i][p][2], acc[i][p][3]);
        }
}

// reduce partials, apply rank-1 norm scaling + temperature, row softmax
__global__ __launch_bounds__(64)
void attn_softmax(const float* __restrict__ temp, const float* __restrict__ inv)
{
    const int bh = blockIdx.x;
    const int b  = bh >> 3;
    const int h  = bh & 7;
    const int r  = threadIdx.x;
    if (r >= DH) return;
    const float* ivq = inv + b * 2 * C_ + h * DH;
    const float* ivk = ivq + C_;
    const float rowscale = ivq[r] * temp[h];

    float vals[DH];
#pragma unroll
    for (int c = 0; c < DH; c++) {
        float s = 0.f;
#pragma unroll
        for (int ch = 0; ch < NCH; ch++)
            s += g_Spart[ch][bh][r * DH + c];
        vals[c] = s * rowscale * ivk[c];
    }
    float m = -INFINITY;
#pragma unroll
    for (int c = 0; c < DH; c++) m = fmaxf(m, vals[c]);
    float sum = 0.f;
#pragma unroll
    for (int c = 0; c < DH; c++) {
        vals[c] = expf(vals[c] - m);
        sum += vals[c];
    }
    float is = 1.f / sum;
#pragma unroll
    for (int c = 0; c < DH; c++)
        g_S[bh][r * DH + c] = vals[c] * is;
}

// ---------------------------------------------------------------------------
// W_eff[b] = W_proj @ blockdiag(A_soft[b]) -> fp16. grid = B_*NH.
// ---------------------------------------------------------------------------
__global__ __launch_bounds__(256)
void weff_kernel(const float* __restrict__ wp, __half* __restrict__ eh)
{
    const int bh = blockIdx.x;
    const int b  = bh >> 3;
    const int h  = bh & 7;
    const int t  = threadIdx.x;

    __shared__ float As[DH][DH + 1];
    for (int i = t; i < DH * DH; i += 256)
        As[i / DH][i % DH] = g_S[bh][i];
    __syncthreads();

    for (int o = t; o < C_; o += 256) {
        float wrow[DH];
#pragma unroll
        for (int d = 0; d < DH; d++) wrow[d] = wp[(size_t)o * C_ + h * DH + d];
#pragma unroll 4
        for (int e = 0; e < DH; e++) {
            float acc = 0.f;
#pragma unroll
            for (int d = 0; d < DH; d++) acc = fmaf(wrow[d], As[d][e], acc);
            eh[((size_t)b * C_ + o) * C_ + h * DH + e] = __float2half(acc);
        }
    }
}

// ---------------------------------------------------------------------------
extern "C" void kernel_launch(void* const* d_in, const int* in_sizes, int n_in,
                              void* d_out, int out_size)
{
    const float* x      = (const float*)d_in[0];
    const float* w_qkv  = (const float*)d_in[1];
    const float* w_dw   = (const float*)d_in[2];
    const float* w_proj = (const float*)d_in[3];
    const float* temp   = (const float*)d_in[4];
    float* out = (float*)d_out;

    float* inv;
    __half *qkv16, *W0, *T0, *We0;
    cudaGetSymbolAddress((void**)&qkv16, g_qkv16);
    cudaGetSymbolAddress((void**)&inv, g_inv);
    cudaGetSymbolAddress((void**)&W0, g_W0);
    cudaGetSymbolAddress((void**)&T0, g_T0);
    cudaGetSymbolAddress((void**)&We0, g_We0);

    cudaFuncSetAttribute(gemm_h1, cudaFuncAttributeMaxDynamicSharedMemorySize, GSMEM);

    // 1) W -> fp16 ; X -> fp16
    wconvert<<<(C3 * C_ + 255) / 256, 256>>>(w_qkv, W0, C3 * C_);
    xconv<<<(B_ * C_ * HW / 4 + 255) / 256, 256>>>(x, T0, B_ * C_ * HW / 4);
    // 2) qkv16 = W_qkv @ X  (fp16 output)
    gemm_h1<<<dim3(C3 / 128, HW / 256, B_), 256, GSMEM>>>(
        W0, 0, T0, (size_t)C_ * HW, qkv16, (size_t)C3 * HW, 1);
    // 3) dwconv in place on fp16 qkv + fused q/k norms
    dwconv3x3<<<B_ * C3, 256>>>(qkv16, w_dw, inv);
    // 4) attention scores via mma (fp16 q/k, unnormalized Gram) + softmax
    attn_scores<<<dim3(NCH, B_ * NH), 96>>>(qkv16);
    attn_softmax<<<B_ * NH, 64>>>(temp, inv);
    // 5) W_eff = W_proj . blockdiag(A) -> fp16
    weff_kernel<<<B_ * NH, 256>>>(w_proj, We0);
    // 6) out = W_eff[b] @ V  (V = fp16 v-plane inside qkv16; fp32 output)
    gemm_h1<<<dim3(C_ / 128, HW / 256, B_), 256, GSMEM>>>(
        We0, (size_t)C_ * C_, qkv16 + (size_t)2 * C_ * HW, (size_t)C3 * HW,
        out, (size_t)C_ * HW, 0);
}

// round 14
// speedup vs baseline: 2.9341x; 1.0428x over previous
#include <cuda_runtime.h>
#include <cuda.h>
#include <cuda_fp16.h>
#include <math.h>
#include <stdint.h>

// Problem constants (fixed shapes)
#define B_   16
#define C_   384
#define C3   1152
#define HW   4096
#define NH   8
#define DH   48
#define NCH  8
#define CHUNK 512
#define EPSN 1e-12f
#define KTOT 384

// GEMM smem geometry: block 128(M) x 256(N) x 32(K), 4-stage cp.async
#define LDA 40
#define LDB 264
#define A_SZ   (128 * LDA * 2)            // 10240
#define B_SZ   (32 * LDB * 2)             // 16896
#define B_OFF  A_SZ
#define SST    (B_OFF + B_SZ)             // 27136
#define NSTG   4
#define GSMEM  (NSTG * SST)               // 108544

// ---------------- scratch (__device__ globals; no runtime alloc) -----------
__device__ __align__(128) __half g_qkv16[(size_t)B_ * C3 * HW];     // 151 MB
__device__ float g_inv[B_ * 2 * C_];
__device__ float g_Spart[NCH][B_ * NH][DH * DH];
__device__ __align__(128) __half g_W0[C3 * C_];                     // Wh [m][k]
__device__ __align__(128) __half g_T0[(size_t)B_ * C_ * HW];        // X fp16 [k][n]
__device__ __align__(128) __half g_We0[B_ * C_ * C_];               // Weh [m][k]

// ---------------- PTX helpers ----------------------------------------------
__device__ __forceinline__ uint32_t smem_u32(const void* p) {
    uint32_t a;
    asm("{ .reg .u64 t; cvta.to.shared.u64 t, %1; cvt.u32.u64 %0, t; }"
        : "=r"(a) : "l"(p));
    return a;
}
__device__ __forceinline__ void ldm_x4(uint32_t* r, uint32_t addr) {
    asm volatile("ldmatrix.sync.aligned.m8n8.x4.shared.b16 {%0,%1,%2,%3}, [%4];"
        : "=r"(r[0]), "=r"(r[1]), "=r"(r[2]), "=r"(r[3]) : "r"(addr));
}
__device__ __forceinline__ void ldm_x4_t(uint32_t* r, uint32_t addr) {
    asm volatile("ldmatrix.sync.aligned.m8n8.x4.trans.shared.b16 {%0,%1,%2,%3}, [%4];"
        : "=r"(r[0]), "=r"(r[1]), "=r"(r[2]), "=r"(r[3]) : "r"(addr));
}
__device__ __forceinline__ void mma_h(float* c, const uint32_t* a,
                                      uint32_t b0, uint32_t b1) {
    asm volatile(
        "mma.sync.aligned.m16n8k16.row.col.f32.f16.f16.f32 "
        "{%0,%1,%2,%3}, {%4,%5,%6,%7}, {%8,%9}, {%0,%1,%2,%3};"
        : "+f"(c[0]), "+f"(c[1]), "+f"(c[2]), "+f"(c[3])
        : "r"(a[0]), "r"(a[1]), "r"(a[2]), "r"(a[3]), "r"(b0), "r"(b1));
}
__device__ __forceinline__ void cpa16(uint32_t s, const void* g) {
    asm volatile("cp.async.cg.shared.global [%0], [%1], 16;" :: "r"(s), "l"(g));
}
__device__ __forceinline__ void cpa_commit() {
    asm volatile("cp.async.commit_group;");
}
template <int N> __device__ __forceinline__ void cpa_wait() {
    asm volatile("cp.async.wait_group %0;" :: "n"(N));
}

// ---------------------------------------------------------------------------
// fp16 GEMM: C[b][M,4096] = A[M,384] @ B[384,4096].  A [m][k]; B [k][n].
// Block 128x256x32, 8 warps (2Mx4N), warp 64x64, 4-stage cp.async,
// SINGLE barrier per k-tile (loads issued post-barrier into stage kt+3).
// outH=1 -> fp16 output; outH=0 -> fp32 output.
// ---------------------------------------------------------------------------
__global__ __launch_bounds__(256, 1)
void gemm_h1(const __half* __restrict__ Ahg, size_t aBatch,
             const __half* __restrict__ Bg, size_t bBatch,
             void* __restrict__ Cvoid, size_t cBatch, int outH)
{
    extern __shared__ char smem[];
    const uint32_t sbase = smem_u32(smem);

    const int t    = threadIdx.x;
    const int lane = t & 31;
    const int wid  = t >> 5;
    const int b    = blockIdx.z;
    const int m0   = blockIdx.x * 128;
    const int n0   = blockIdx.y * 256;
    const int warpM = (wid >> 2) * 64;
    const int warpN = (wid & 3) * 64;

    const __half* Asrc = Ahg + (size_t)b * aBatch + (size_t)m0 * KTOT;
    const __half* Bsrc = Bg + (size_t)b * bBatch;

    const int g  = lane >> 3;
    const int lr = lane & 7;
    const uint32_t aLane = (uint32_t)(((g & 1) * 8 + lr) * LDA + (g >> 1) * 8) * 2;
    const uint32_t bLane = (uint32_t)(((g & 1) * 8 + lr) * LDB + (g >> 1) * 8) * 2;

    float acc[4][8][4];
#pragma unroll
    for (int i = 0; i < 4; i++)
#pragma unroll
        for (int j = 0; j < 8; j++)
#pragma unroll
            for (int e = 0; e < 4; e++) acc[i][j][e] = 0.f;

    auto load_stage = [&](int kt, int stg) {
        const uint32_t sb = sbase + stg * SST;
#pragma unroll
        for (int it = 0; it < 2; it++) {          // A: 512 x 16B
            int c = t + it * 256;
            int r = c >> 2, kc = c & 3;
            cpa16(sb + r * (LDA * 2) + kc * 16,
                  Asrc + (size_t)r * KTOT + kt * 32 + kc * 8);
        }
#pragma unroll
        for (int it = 0; it < 4; it++) {          // B: 1024 x 16B
            int c = t + it * 256;
            int r = c >> 5, nc = c & 31;
            cpa16(sb + B_OFF + r * (LDB * 2) + nc * 16,
                  Bsrc + (size_t)(kt * 32 + r) * HW + n0 + nc * 8);
        }
        cpa_commit();
    };

    const int KT = KTOT / 32;   // 12
    load_stage(0, 0);
    load_stage(1, 1);
    load_stage(2, 2);

    for (int kt = 0; kt < KT; kt++) {
        const int rem = KT - 1 - kt;
        if (rem >= 2)      cpa_wait<2>();
        else if (rem == 1) cpa_wait<1>();
        else               cpa_wait<0>();
        __syncthreads();
        // safe: barrier above guarantees all warps finished reading stage
        // (kt-1)%4 == (kt+3)%4 during iteration kt-1.
        if (kt + 3 < KT) load_stage(kt + 3, (kt + 3) % NSTG);

        const uint32_t sb = sbase + (kt % NSTG) * SST;
#pragma unroll
        for (int k16 = 0; k16 < 2; k16++) {
            uint32_t Ah[4][4];
#pragma unroll
            for (int i = 0; i < 4; i++)
                ldm_x4(Ah[i], sb + aLane
                              + (uint32_t)((warpM + i * 16) * LDA + k16 * 16) * 2);
            uint32_t Bf[8][2];
#pragma unroll
            for (int p = 0; p < 4; p++) {
                uint32_t r[4];
                uint32_t bo = sb + B_OFF + bLane
                            + (uint32_t)(k16 * 16 * LDB + warpN + p * 16) * 2;
                ldm_x4_t(r, bo);
                Bf[p * 2][0] = r[0]; Bf[p * 2][1] = r[1];
                Bf[p * 2 + 1][0] = r[2]; Bf[p * 2 + 1][1] = r[3];
            }
#pragma unroll
            for (int i = 0; i < 4; i++)
#pragma unroll
                for (int j = 0; j < 8; j++)
                    mma_h(acc[i][j], Ah[i], Bf[j][0], Bf[j][1]);
        }
    }

    const int erow = lane >> 2;
    const int ecol = (lane & 3) * 2;
    if (outH) {
        __half* Cp = (__half*)Cvoid + (size_t)b * cBatch;
#pragma unroll
        for (int i = 0; i < 4; i++)
#pragma unroll
            for (int j = 0; j < 8; j++) {
                __half* base = Cp + (size_t)(m0 + warpM + i * 16 + erow) * HW
                                  + n0 + warpN + j * 8 + ecol;
                __half2 v01 = __floats2half2_rn(acc[i][j][0], acc[i][j][1]);
                __half2 v23 = __floats2half2_rn(acc[i][j][2], acc[i][j][3]);
                *(__half2*)base = v01;
                *(__half2*)(base + 8 * HW) = v23;
            }
    } else {
        float* Cp = (float*)Cvoid + (size_t)b * cBatch;
#pragma unroll
        for (int i = 0; i < 4; i++)
#pragma unroll
            for (int j = 0; j < 8; j++) {
                float* base = Cp + (size_t)(m0 + warpM + i * 16 + erow) * HW
                                 + n0 + warpN + j * 8 + ecol;
                *(float2*)base = make_float2(acc[i][j][0], acc[i][j][1]);
                *(float2*)(base + 8 * HW) = make_float2(acc[i][j][2], acc[i][j][3]);
            }
    }
}

// ---------------------------------------------------------------------------
// Combined fp32 -> fp16 convert for X (first nx4 float4's) and W (next nw4).
// ---------------------------------------------------------------------------
__global__ __launch_bounds__(256)
void convprep(const float* __restrict__ x, __half* __restrict__ xh, int nx4,
              const float* __restrict__ w, __half* __restrict__ wh, int nw4)
{
    int i = blockIdx.x * 256 + threadIdx.x;
    const float* src;
    __half* dst;
    int j;
    if (i < nx4)            { src = x; dst = xh; j = i; }
    else if (i < nx4 + nw4) { src = w; dst = wh; j = i - nx4; }
    else return;
    float4 v = ((const float4*)src)[j];
    __half2 a = __floats2half2_rn(v.x, v.y);
    __half2 b = __floats2half2_rn(v.z, v.w);
    ((uint2*)dst)[j] = make_uint2(*(uint32_t*)&a, *(uint32_t*)&b);
}

// ---------------------------------------------------------------------------
// Depthwise 3x3 SAME conv on fp16 qkv, in place. fp16 smem staging,
// halo-only zeroing, fp32 stencil math, fused q/k inv L2 norms.
// ---------------------------------------------------------------------------
__global__ __launch_bounds__(256)
void dwconv3x3(__half* __restrict__ qkv, const float* __restrict__ wdw,
               float* __restrict__ inv)
{
    const int plane = blockIdx.x;
    const int b     = plane / C3;
    const int ch    = plane % C3;
    __half* p = qkv + (size_t)plane * HW;

    __shared__ __align__(16) __half s[66][88];   // 176 B rows
    const int t = threadIdx.x;

    // halo zeroing: col halo (rows 1..64, cols 6,7,72,73) = 256 cells, 1/thread
    {
        const int hr = (t >> 2) + 1;
        const int hc = (t & 1) ? 7 : 6;
        s[hr][hc + ((t & 2) ? 66 : 0)] = __ushort_as_half(0);  // cols 6/7/72/73
        if (t < 88) { s[0][t] = __ushort_as_half(0); s[65][t] = __ushort_as_half(0); }
    }
    // interior fill (rows 1..64, cols 8..71) — disjoint from halo cells
#pragma unroll
    for (int it = 0; it < 2; it++) {
        int i = t + it * 256;
        int y = i >> 3, x8 = (i & 7) * 8;
        *(uint4*)&s[y + 1][x8 + 8] = *(const uint4*)&p[y * 64 + x8];
    }

    float w[9];
#pragma unroll
    for (int j = 0; j < 9; j++) w[j] = wdw[ch * 9 + j];
    __syncthreads();

    const int y  = (t >> 3) * 2;
    const int x8 = (t & 7) * 8;

    float v[4][12];
#pragma unroll
    for (int r = 0; r < 4; r++) {
        __half2 hh[12];
        *(uint4*)&hh[0] = *(uint4*)&s[y + r][x8];
        *(uint4*)&hh[4] = *(uint4*)&s[y + r][x8 + 8];
        *(uint4*)&hh[8] = *(uint4*)&s[y + r][x8 + 16];
#pragma unroll
        for (int u = 0; u < 6; u++) {
            float2 f = __half22float2(hh[3 + u]);
            v[r][2 * u]     = f.x;
            v[r][2 * u + 1] = f.y;
        }
    }

    float o[2][8];
#pragma unroll
    for (int rr = 0; rr < 2; rr++)
#pragma unroll
        for (int j = 0; j < 8; j++) {
            float a = 0.f;
#pragma unroll
            for (int dy = 0; dy < 3; dy++)
#pragma unroll
                for (int dx = 0; dx < 3; dx++)
                    a = fmaf(v[rr + dy][j + 1 + dx], w[dy * 3 + dx], a);
            o[rr][j] = a;
        }

    float ss = 0.f;
#pragma unroll
    for (int rr = 0; rr < 2; rr++) {
        __half2 h0 = __floats2half2_rn(o[rr][0], o[rr][1]);
        __half2 h1 = __floats2half2_rn(o[rr][2], o[rr][3]);
        __half2 h2 = __floats2half2_rn(o[rr][4], o[rr][5]);
        __half2 h3 = __floats2half2_rn(o[rr][6], o[rr][7]);
        *(uint4*)&p[(y + rr) * 64 + x8] = make_uint4(
            *(uint32_t*)&h0, *(uint32_t*)&h1, *(uint32_t*)&h2, *(uint32_t*)&h3);
#pragma unroll
        for (int j = 0; j < 8; j++) ss = fmaf(o[rr][j], o[rr][j], ss);
    }

    if (ch < 2 * C_) {
        for (int off = 16; off > 0; off >>= 1)
            ss += __shfl_down_sync(0xffffffffu, ss, off);
        __shared__ float red[8];
        if ((t & 31) == 0) red[t >> 5] = ss;
        __syncthreads();
        if (t == 0) {
            float tot = 0.f;
#pragma unroll
            for (int i = 0; i < 8; i++) tot += red[i];
            inv[b * 2 * C_ + ch] = 1.f / fmaxf(sqrtf(tot), EPSN);
        }
    }
}

// ---------------------------------------------------------------------------
// Attention scores via mma.sync (partial unnormalized Gram; from R13, passing)
// ---------------------------------------------------------------------------
#define LDQ 72
__global__ __launch_bounds__(96)
void attn_scores(const __half* __restrict__ qkv)
{
    const int bh    = blockIdx.y;
    const int b     = bh >> 3;
    const int h     = bh & 7;
    const int chunk = blockIdx.x;
    const int t    = threadIdx.x;
    const int lane = t & 31;
    const int wid  = t >> 5;

    const __half* qbase = qkv + ((size_t)b * C3 + h * DH) * HW;
    const __half* kbase = qbase + (size_t)C_ * HW;

    __shared__ __align__(16) __half Qs[DH][LDQ];
    __shared__ __align__(16) __half Ks[DH][LDQ];
    const uint32_t qb = smem_u32(&Qs[0][0]);
    const uint32_t kb2 = smem_u32(&Ks[0][0]);

    const int g  = lane >> 3;
    const int lr = lane & 7;
    const uint32_t aLane = (uint32_t)(((g & 1) * 8 + lr) * LDQ + (g >> 1) * 8) * 2;
    const uint32_t bLane = (uint32_t)((wid * 16 + (g >> 1) * 8 + lr) * LDQ + (g & 1) * 8) * 2;

    float acc[3][2][4];
#pragma unroll
    for (int i = 0; i < 3; i++)
#pragma unroll
        for (int p = 0; p < 2; p++)
#pragma unroll
            for (int e = 0; e < 4; e++) acc[i][p][e] = 0.f;

    const int kb0 = chunk * CHUNK;
    for (int kt = 0; kt < CHUNK / 64; kt++) {
        for (int i = t; i < DH * 8; i += 96) {
            int r  = i >> 3;
            int c8 = (i & 7) * 8;
            *(uint4*)&Qs[r][c8] = *(const uint4*)&qbase[(size_t)r * HW + kb0 + kt * 64 + c8];
            *(uint4*)&Ks[r][c8] = *(const uint4*)&kbase[(size_t)r * HW + kb0 + kt * 64 + c8];
        }
        __syncthreads();

#pragma unroll
        for (int k16 = 0; k16 < 4; k16++) {
            uint32_t Aq[3][4];
#pragma unroll
            for (int i = 0; i < 3; i++)
                ldm_x4(Aq[i], qb + aLane + (uint32_t)(i * 16 * LDQ + k16 * 16) * 2);
            uint32_t r[4];
            ldm_x4(r, kb2 + bLane + (uint32_t)(k16 * 16) * 2);
#pragma unroll
            for (int i = 0; i < 3; i++) {
                mma_h(acc[i][0], Aq[i], r[0], r[1]);
                mma_h(acc[i][1], Aq[i], r[2], r[3]);
            }
        }
        __syncthreads();
    }

    const int erow = lane >> 2;
    const int ecol = (lane & 3) * 2;
    float* sp = &g_Spart[chunk][bh][0];
#pragma unroll
    for (int i = 0; i < 3; i++)
#pragma unroll
        for (int p = 0; p < 2; p++) {
            float* base = sp + (i * 16 + erow) * DH + wid * 16 + p * 8 + ecol;
            *(float2*)base = make_float2(acc[i][p][0], acc[i][p][1]);
            *(float2*)(base + 8 * DH) = make_float2(acc[i][p][2], acc[i][p][3]);
        }
}

// ---------------------------------------------------------------------------
// FUSED: reduce partials + rank-1 norm scaling + temperature + softmax +
// W_eff = W_proj @ blockdiag(A) -> fp16.  grid = B_*NH, 256 threads.
// ---------------------------------------------------------------------------
__global__ __launch_bounds__(256)
void soft_weff(const float* __restrict__ temp, const float* __restrict__ inv,
               const float* __restrict__ wp, __half* __restrict__ eh)
{
    const int bh = blockIdx.x;
    const int b  = bh >> 3;
    const int h  = bh & 7;
    const int t  = threadIdx.x;

    __shared__ float As[DH][DH + 1];
    // parallel reduction of the 8 split-K partials
    for (int i = t; i < DH * DH; i += 256) {
        float s = 0.f;
#pragma unroll
        for (int ch = 0; ch < NCH; ch++)
            s += g_Spart[ch][bh][i];
        As[i / DH][i % DH] = s;
    }
    __syncthreads();

    // row softmax with norm scaling (threads 0..47)
    if (t < DH) {
        const float* ivq = inv + b * 2 * C_ + h * DH;
        const float* ivk = ivq + C_;
        const float rowscale = ivq[t] * temp[h];
        float vals[DH];
        float m = -INFINITY;
#pragma unroll
        for (int c = 0; c < DH; c++) {
            vals[c] = As[t][c] * rowscale * ivk[c];
            m = fmaxf(m, vals[c]);
        }
        float sum = 0.f;
#pragma unroll
        for (int c = 0; c < DH; c++) {
            vals[c] = expf(vals[c] - m);
            sum += vals[c];
        }
        float is = 1.f / sum;
#pragma unroll
        for (int c = 0; c < DH; c++) As[t][c] = vals[c] * is;
    }
    __syncthreads();

    // W_eff rows
    for (int o = t; o < C_; o += 256) {
        float wrow[DH];
#pragma unroll
        for (int d = 0; d < DH; d++) wrow[d] = wp[(size_t)o * C_ + h * DH + d];
#pragma unroll 4
        for (int e = 0; e < DH; e++) {
            float acc = 0.f;
#pragma unroll
            for (int d = 0; d < DH; d++) acc = fmaf(wrow[d], As[d][e], acc);
            eh[((size_t)b * C_ + o) * C_ + h * DH + e] = __float2half(acc);
        }
    }
}

// ---------------------------------------------------------------------------
extern "C" void kernel_launch(void* const* d_in, const int* in_sizes, int n_in,
                              void* d_out, int out_size)
{
    const float* x      = (const float*)d_in[0];
    const float* w_qkv  = (const float*)d_in[1];
    const float* w_dw   = (const float*)d_in[2];
    const float* w_proj = (const float*)d_in[3];
    const float* temp   = (const float*)d_in[4];
    float* out = (float*)d_out;

    float* inv;
    __half *qkv16, *W0, *T0, *We0;
    cudaGetSymbolAddress((void**)&qkv16, g_qkv16);
    cudaGetSymbolAddress((void**)&inv, g_inv);
    cudaGetSymbolAddress((void**)&W0, g_W0);
    cudaGetSymbolAddress((void**)&T0, g_T0);
    cudaGetSymbolAddress((void**)&We0, g_We0);

    cudaFuncSetAttribute(gemm_h1, cudaFuncAttributeMaxDynamicSharedMemorySize, GSMEM);

    const int nx4 = B_ * C_ * HW / 4;
    const int nw4 = C3 * C_ / 4;
    // 1) X,W -> fp16 (one launch)
    convprep<<<(nx4 + nw4 + 255) / 256, 256>>>(x, T0, nx4, w_qkv, W0, nw4);
    // 2) qkv16 = W_qkv @ X  (fp16 output)
    gemm_h1<<<dim3(C3 / 128, HW / 256, B_), 256, GSMEM>>>(
        W0, 0, T0, (size_t)C_ * HW, qkv16, (size_t)C3 * HW, 1);
    // 3) dwconv in place on fp16 qkv + fused q/k norms
    dwconv3x3<<<B_ * C3, 256>>>(qkv16, w_dw, inv);
    // 4) attention scores via mma
    attn_scores<<<dim3(NCH, B_ * NH), 96>>>(qkv16);
    // 5) fused softmax + W_eff
    soft_weff<<<B_ * NH, 256>>>(temp, inv, w_proj, We0);
    // 6) out = W_eff[b] @ V  (fp32 output)
    gemm_h1<<<dim3(C_ / 128, HW / 256, B_), 256, GSMEM>>>(
        We0, (size_t)C_ * C_, qkv16 + (size_t)2 * C_ * HW, (size_t)C3 * HW,
        out, (size_t)C_ * HW, 0);
}